// round 10
// baseline (speedup 1.0000x reference)
#include <cuda_runtime.h>
#include <cuda_bf16.h>
#include <cstdint>

#define NPTS 8192
#define DIMX 256
#define DIMZ 64
#define KNN  5
#define EPSF 1e-7f

#define TS   128                           // tile size
#define NT2  64                            // 8192 / 128 tiles
#define NPAIRS2 (NT2 * (NT2 + 1) / 2)      // 2080
#define PTOP 4
#define GTOP 8
#define U64MAX 0xFFFFFFFFFFFFFFFFull
#define SMCS 129                           // smC row stride in floats (64 x 128 tile + pad)

// ---- scratch ----
__device__ float g_sq[NPTS];
__device__ __nv_bfloat16 g_xbf[NPTS * DIMX];
__device__ unsigned long long g_p[(size_t)NPTS * NT2 * PTOP];   // 16.8 MB
__device__ int   g_cand[NPTS][GTOP];
__device__ float g_bsum[1024];

__device__ __forceinline__ uint32_t smem_u32(const void* p) {
    uint32_t a;
    asm("{ .reg .u64 t; cvta.to.shared.u64 t, %1; cvt.u32.u64 %0, t; }" : "=r"(a) : "l"(p));
    return a;
}

#define LDSM_X4(r0, r1, r2, r3, addr) \
    asm volatile("ldmatrix.sync.aligned.m8n8.x4.shared.b16 {%0,%1,%2,%3}, [%4];" \
                 : "=r"(r0), "=r"(r1), "=r"(r2), "=r"(r3) : "r"(addr))

#define MMA16816(c, a0, a1, a2, a3, b0, b1) \
    asm volatile("mma.sync.aligned.m16n8k16.row.col.f32.bf16.bf16.f32 " \
                 "{%0,%1,%2,%3}, {%4,%5,%6,%7}, {%8,%9}, {%0,%1,%2,%3};" \
                 : "+f"((c)[0]), "+f"((c)[1]), "+f"((c)[2]), "+f"((c)[3]) \
                 : "r"(a0), "r"(a1), "r"(a2), "r"(a3), "r"(b0), "r"(b1))

// monotone float->u32; key = (enc<<32)|idx : u64 '<' == lexicographic (val,idx)
__device__ __forceinline__ unsigned long long packkey(float v, int idx) {
    uint32_t u = __float_as_uint(v);
    u = (u >> 31) ? ~u : (u | 0x80000000u);
    return ((unsigned long long)u << 32) | (uint32_t)idx;
}
template<int NL>
__device__ __forceinline__ void insertU(unsigned long long l[NL], unsigned long long v) {
    if (v < l[NL - 1]) {
        l[NL - 1] = v;
#pragma unroll
        for (int s = NL - 1; s > 0; --s)
            if (l[s] < l[s - 1]) { unsigned long long t = l[s]; l[s] = l[s - 1]; l[s - 1] = t; }
    }
}
__device__ __forceinline__ bool lessp(float v, int i, float v2, int i2) {
    return (v < v2) || (v == v2 && i < i2);
}
__device__ __forceinline__ void insert5(float lv[KNN], int li[KNN], float v, int idx) {
    if (lessp(v, idx, lv[KNN - 1], li[KNN - 1])) {
        lv[KNN - 1] = v; li[KNN - 1] = idx;
#pragma unroll
        for (int s = KNN - 1; s > 0; --s) {
            if (lessp(lv[s], li[s], lv[s - 1], li[s - 1])) {
                float tv = lv[s]; lv[s] = lv[s - 1]; lv[s - 1] = tv;
                int   ti = li[s]; li[s] = li[s - 1]; li[s - 1] = ti;
            }
        }
    }
}

// ================= fused fp32->bf16 + squared row norms =================
__global__ void cvtsq_kernel(const float* __restrict__ X) {
    int warp = (blockIdx.x * blockDim.x + threadIdx.x) >> 5;
    int lane = threadIdx.x & 31;
    if (warp >= NPTS) return;
    const float2* src = (const float2*)(X + (size_t)warp * DIMX);
    __nv_bfloat162* dst = (__nv_bfloat162*)(g_xbf + (size_t)warp * DIMX);
    float s = 0.f;
#pragma unroll
    for (int t = 0; t < 4; ++t) {
        float2 v = src[lane + 32 * t];
        s = fmaf(v.x, v.x, fmaf(v.y, v.y, s));
        dst[lane + 32 * t] = __floats2bfloat162_rn(v.x, v.y);
    }
#pragma unroll
    for (int o = 16; o > 0; o >>= 1) s += __shfl_xor_sync(0xffffffffu, s, o);
    if (lane == 0) g_sq[warp] = s;
}

// ====== symmetric 128x128 tile-pair screen: 512 thr, 16 warps, 2-pass epilogue ======
__global__ __launch_bounds__(512) void screen_pair_kernel() {
    // stage buffers: smA [0,16K) + smB [16K,32K).  smC (64 x SMCS floats = 33024 B)
    // overlays the WHOLE region after the mainloop (both are dead by then).
    __shared__ __align__(16) uint8_t smRaw[64 * SMCS * 4];
    __shared__ float sqI[TS], sqJ[TS];
    uint8_t* smA = smRaw;
    uint8_t* smB = smRaw + 16384;
    float* smC = (float*)smRaw;

    const int tid = threadIdx.x;
    const int wid = tid >> 5;
    const int lane = tid & 31;
    const int wr = wid >> 2;       // warp row 0..3 (32 rows each)
    const int wc = wid & 3;        // warp col 0..3 (32 cols each)

    // ---- linear pair index -> (ti, tj), ti <= tj ----
    const int k = blockIdx.x;
    int i = (int)(64.5f - sqrtf(64.5f * 64.5f - 2.0f * (float)k));
    if (i < 0) i = 0; if (i > NT2 - 1) i = NT2 - 1;
    while (i > 0 && (i * NT2 - i * (i - 1) / 2) > k) --i;
    while (((i + 1) * NT2 - (i + 1) * i / 2) <= k) ++i;
    const int ti = i;
    const int tj = i + (k - (i * NT2 - i * (i - 1) / 2));
    const int rbI = ti * TS, rbJ = tj * TS;

    if (tid < TS) { sqI[tid] = g_sq[rbI + tid]; sqJ[tid] = g_sq[rbJ + tid]; }

    // staging: 128 rows x 8 chunks(16B) per tile k-chunk; thread covers rows rr, rr+64
    const int rr = tid >> 3, cc = tid & 7;

    uint4 pa[2], pb[2];
#pragma unroll
    for (int it = 0; it < 2; ++it) {
        pa[it] = *(const uint4*)(g_xbf + (size_t)(rbI + rr + it * 64) * DIMX + cc * 8);
        pb[it] = *(const uint4*)(g_xbf + (size_t)(rbJ + rr + it * 64) * DIMX + cc * 8);
    }

    float c[2][4][4];
#pragma unroll
    for (int m = 0; m < 2; ++m)
#pragma unroll
        for (int j = 0; j < 4; ++j)
#pragma unroll
            for (int q = 0; q < 4; ++q) c[m][j][q] = 0.f;

    // fragment addressing
    const int rA0 = wr * 32 + (lane & 15);           // m-frag 0 row; m-frag 1 = +16
    const uint32_t aBase = smem_u32(smA);
    const uint32_t aHi = (uint32_t)(lane >> 4);
    const int bLane = (lane & 7) + ((lane >> 4) << 3);
    const uint32_t bBase = smem_u32(smB);
    const uint32_t bSw = (uint32_t)(lane & 7);
    const uint32_t bHi = (uint32_t)((lane >> 3) & 1);

    for (int kc = 0; kc < 4; ++kc) {
        __syncthreads();
#pragma unroll
        for (int it = 0; it < 2; ++it) {
            int r = rr + it * 64;
            uint32_t off = (uint32_t)r * 128 + (((uint32_t)cc ^ (r & 7)) << 4);
            *(uint4*)(smA + off) = pa[it];
            *(uint4*)(smB + off) = pb[it];
        }
        __syncthreads();
        if (kc < 3) {
#pragma unroll
            for (int it = 0; it < 2; ++it) {
                pa[it] = *(const uint4*)(g_xbf + (size_t)(rbI + rr + it * 64) * DIMX + (kc + 1) * 64 + cc * 8);
                pb[it] = *(const uint4*)(g_xbf + (size_t)(rbJ + rr + it * 64) * DIMX + (kc + 1) * 64 + cc * 8);
            }
        }
#pragma unroll
        for (int ks = 0; ks < 4; ++ks) {
            uint32_t a[2][4];
#pragma unroll
            for (int m = 0; m < 2; ++m) {
                int rA = rA0 + m * 16;
                LDSM_X4(a[m][0], a[m][1], a[m][2], a[m][3],
                        aBase + (uint32_t)rA * 128 + ((((uint32_t)ks * 2 + aHi) ^ (uint32_t)(rA & 7)) << 4));
            }
            uint32_t ccB = (((uint32_t)ks * 2 + bHi) ^ bSw) << 4;
#pragma unroll
            for (int p = 0; p < 2; ++p) {
                int bRow = wc * 32 + p * 16 + bLane;
                uint32_t b0, b1, b2, b3;
                LDSM_X4(b0, b1, b2, b3, bBase + (uint32_t)bRow * 128 + ccB);
#pragma unroll
                for (int m = 0; m < 2; ++m) {
                    MMA16816(c[m][2 * p],     a[m][0], a[m][1], a[m][2], a[m][3], b0, b1);
                    MMA16816(c[m][2 * p + 1], a[m][0], a[m][1], a[m][2], a[m][3], b2, b3);
                }
            }
        }
    }
    __syncthreads();   // all LDSM reads done; smC may overlay stage buffers

    // col-side accumulator (persists across both passes)
    unsigned long long lc[PTOP];
#pragma unroll
    for (int s = 0; s < PTOP; ++s) lc[s] = U64MAX;
    const int c_local = tid >> 2;     // 0..127: this thread's col point
    const int h4 = tid & 3;           // 4 scanners per col

    // ---- two passes over row halves (each pass: 64 rows x 128 cols in smC) ----
    for (int h = 0; h < 2; ++h) {
        // warps owning this half stage their C rows into smC[64][SMCS]
        if ((wid >> 3) == h) {
#pragma unroll
            for (int m = 0; m < 2; ++m) {
                int lr0 = (wr & 1) * 32 + m * 16 + (lane >> 2), lr1 = lr0 + 8;
                int colB = wc * 32 + 2 * (lane & 3);
#pragma unroll
                for (int j = 0; j < 4; ++j) {
                    int col = colB + j * 8;
                    smC[lr0 * SMCS + col]     = c[m][j][0];
                    smC[lr0 * SMCS + col + 1] = c[m][j][1];
                    smC[lr1 * SMCS + col]     = c[m][j][2];
                    smC[lr1 * SMCS + col + 1] = c[m][j][3];
                }
            }
        }
        __syncthreads();

        // row side: 8 scanners/row over 128 cols, interleaved
        {
            const int r_local = tid >> 3, h8 = tid & 7;
            const int grow = rbI + h * 64 + r_local;
            unsigned long long l[PTOP];
#pragma unroll
            for (int s = 0; s < PTOP; ++s) l[s] = U64MAX;
#pragma unroll
            for (int s = 0; s < 16; ++s) {
                int cl = h8 + 8 * s;
                int idx = rbJ + cl;
                if (idx != grow)
                    insertU<PTOP>(l, packkey(fmaf(-2.f, smC[r_local * SMCS + cl], sqJ[cl]), idx));
            }
#pragma unroll
            for (int d = 1; d < 8; d <<= 1) {
                unsigned long long rv[PTOP];
#pragma unroll
                for (int s = 0; s < PTOP; ++s) rv[s] = __shfl_xor_sync(0xffffffffu, l[s], d);
                for (int s = 0; s < PTOP; ++s) {
                    if (rv[s] >= l[PTOP - 1]) break;
                    insertU<PTOP>(l, rv[s]);
                }
            }
            if (h8 == 0) {
                unsigned long long* dst = &g_p[((size_t)grow * NT2 + tj) * PTOP];
                ((ulonglong2*)dst)[0] = make_ulonglong2(l[0], l[1]);
                ((ulonglong2*)dst)[1] = make_ulonglong2(l[2], l[3]);
            }
        }

        // col side: accumulate over this half's 64 rows (skip for diagonal pair)
        if (ti != tj) {
#pragma unroll
            for (int s = 0; s < 16; ++s) {
                int lr = h4 + 4 * s;                 // local row in smC
                int rl = h * 64 + lr;                // row within tile I
                insertU<PTOP>(lc, packkey(fmaf(-2.f, smC[lr * SMCS + c_local], sqI[rl]), rbI + rl));
            }
        }
        __syncthreads();   // done reading smC before next half overwrites
    }

    // merge col-side scanners (4 consecutive lanes per col) and store
    if (ti != tj) {
#pragma unroll
        for (int d = 1; d < 4; d <<= 1) {
            unsigned long long rv[PTOP];
#pragma unroll
            for (int s = 0; s < PTOP; ++s) rv[s] = __shfl_xor_sync(0xffffffffu, lc[s], d);
            for (int s = 0; s < PTOP; ++s) {
                if (rv[s] >= lc[PTOP - 1]) break;
                insertU<PTOP>(lc, rv[s]);
            }
        }
        if (h4 == 0) {
            unsigned long long* dst = &g_p[((size_t)(rbJ + c_local) * NT2 + ti) * PTOP];
            ((ulonglong2*)dst)[0] = make_ulonglong2(lc[0], lc[1]);
            ((ulonglong2*)dst)[1] = make_ulonglong2(lc[2], lc[3]);
        }
    }
}

// ======= merge: warp per row, 64 sorted lists, early-break =======
__global__ void merge_kernel() {
    int warp = (blockIdx.x * blockDim.x + threadIdx.x) >> 5;
    int lane = threadIdx.x & 31;
    if (warp >= NPTS) return;
    unsigned long long l[GTOP];
#pragma unroll
    for (int s = 0; s < GTOP; ++s) l[s] = U64MAX;
#pragma unroll
    for (int q = 0; q < 2; ++q) {
        const unsigned long long* src = &g_p[((size_t)warp * NT2 + lane + q * 32) * PTOP];
        ulonglong2 v0 = ((const ulonglong2*)src)[0];
        ulonglong2 v1 = ((const ulonglong2*)src)[1];
        if (v0.x >= l[GTOP - 1]) continue;
        insertU<GTOP>(l, v0.x);
        if (v0.y >= l[GTOP - 1]) continue;
        insertU<GTOP>(l, v0.y);
        if (v1.x >= l[GTOP - 1]) continue;
        insertU<GTOP>(l, v1.x);
        if (v1.y < l[GTOP - 1]) insertU<GTOP>(l, v1.y);
    }
#pragma unroll
    for (int d = 1; d < 32; d <<= 1) {
        unsigned long long rv[GTOP];
#pragma unroll
        for (int s = 0; s < GTOP; ++s) rv[s] = __shfl_xor_sync(0xffffffffu, l[s], d);
        for (int s = 0; s < GTOP; ++s) {
            if (rv[s] >= l[GTOP - 1]) break;
            insertU<GTOP>(l, rv[s]);
        }
    }
    if (lane == 0) {
#pragma unroll
        for (int s = 0; s < GTOP; ++s) g_cand[warp][s] = (int)(uint32_t)(l[s] & 0xffffffffu);
    }
}

// ===== fused: exact fp32 re-rank -> lid_X -> z-distances -> lid_Z -> block sum =====
__global__ __launch_bounds__(256) void rerank_z_kernel(const float* __restrict__ X,
                                                       const float* __restrict__ Z) {
    __shared__ float bsum[8];
    const int warp = (blockIdx.x * blockDim.x + threadIdx.x) >> 5;
    const int lane = threadIdx.x & 31;
    const int wid = threadIdx.x >> 5;
    const int row = warp;

    float xi[8];
#pragma unroll
    for (int t = 0; t < 8; ++t) xi[t] = X[(size_t)row * DIMX + lane + 32 * t];
    const float sqr = g_sq[row];

    float lv[KNN]; int li[KNN];
#pragma unroll
    for (int s = 0; s < KNN; ++s) { lv[s] = 3.4e38f; li[s] = 0x7fffffff; }

#pragma unroll
    for (int s = 0; s < GTOP; ++s) {
        int j = g_cand[row][s];
        const float* xr = X + (size_t)j * DIMX;
        float d = 0.f;
#pragma unroll
        for (int t = 0; t < 8; ++t) d = fmaf(xi[t], xr[lane + 32 * t], d);
#pragma unroll
        for (int o = 16; o > 0; o >>= 1) d += __shfl_xor_sync(0xffffffffu, d, o);
        insert5(lv, li, sqr + g_sq[j] - 2.f * d, j);
    }

    float lidX;
    {
        float vK = sqrtf(fmaxf(lv[KNN - 1], 0.f)) + EPSF;
        float lgK = log10f(vK);
        lidX = 0.f;
#pragma unroll
        for (int s = 0; s < KNN; ++s)
            lidX += lgK - log10f(sqrtf(fmaxf(lv[s], 0.f)) + EPSF);
    }

    float z0 = Z[(size_t)row * DIMZ + lane];
    float z1 = Z[(size_t)row * DIMZ + 32 + lane];
    float e[KNN];
#pragma unroll
    for (int s = 0; s < KNN; ++s) {
        int m = li[s];
        float d0 = z0 - Z[(size_t)m * DIMZ + lane];
        float d1 = z1 - Z[(size_t)m * DIMZ + 32 + lane];
        float ss = fmaf(d0, d0, d1 * d1);
#pragma unroll
        for (int o = 16; o > 0; o >>= 1) ss += __shfl_xor_sync(0xffffffffu, ss, o);
        e[s] = sqrtf(ss) + EPSF;
    }
    float lgK = log10f(e[KNN - 1]);
    float lidZ = 0.f;
#pragma unroll
    for (int s = 0; s < KNN; ++s) lidZ += lgK - log10f(e[s]);
    float d = lidX - lidZ;

    if (lane == 0) bsum[wid] = d * d;
    __syncthreads();
    if (threadIdx.x == 0) {
        float s = 0.f;
#pragma unroll
        for (int w = 0; w < 8; ++w) s += bsum[w];
        g_bsum[blockIdx.x] = s;
    }
}

// ================= final deterministic reduction =================
__global__ void final_reduce(float* __restrict__ out) {
    __shared__ float sh[256];
    int t = threadIdx.x;
    float s = g_bsum[t] + g_bsum[t + 256] + g_bsum[t + 512] + g_bsum[t + 768];
    sh[t] = s;
    __syncthreads();
    for (int o = 128; o > 0; o >>= 1) {
        if (t < o) sh[t] += sh[t + o];
        __syncthreads();
    }
    if (t == 0) out[0] = sh[0] * (1.f / ((float)NPTS * KNN * 10.f));
}

extern "C" void kernel_launch(void* const* d_in, const int* in_sizes, int n_in,
                              void* d_out, int out_size) {
    const float* X = (const float*)d_in[0];   // (8192, 256)
    const float* Z = (const float*)d_in[1];   // (8192, 64)
    float* out = (float*)d_out;

    cvtsq_kernel<<<NPTS / 8, 256>>>(X);
    screen_pair_kernel<<<NPAIRS2, 512>>>();
    merge_kernel<<<NPTS / 8, 256>>>();
    rerank_z_kernel<<<NPTS / 8, 256>>>(X, Z);
    final_reduce<<<1, 256>>>(out);
}

// round 11
// speedup vs baseline: 1.7017x; 1.7017x over previous
#include <cuda_runtime.h>
#include <cuda_bf16.h>
#include <cstdint>

#define NPTS 8192
#define DIMX 256
#define DIMZ 64
#define KNN  5
#define EPSF 1e-7f

#define NTILE 128                          // 8192 / 64 row-tiles
#define NPAIRS (NTILE * (NTILE + 1) / 2)   // 8256
#define PTOP 4
#define GTOP 8
#define U64MAX 0xFFFFFFFFFFFFFFFFull

// ---- scratch ----
__device__ float g_sq[NPTS];
__device__ __nv_bfloat16 g_xbf[NPTS * DIMX];
__device__ unsigned long long g_p[(size_t)NPTS * NTILE * PTOP];   // 33.5 MB
__device__ int   g_cand[NPTS][GTOP];
__device__ float g_bsum[1024];

__device__ __forceinline__ uint32_t smem_u32(const void* p) {
    uint32_t a;
    asm("{ .reg .u64 t; cvta.to.shared.u64 t, %1; cvt.u32.u64 %0, t; }" : "=r"(a) : "l"(p));
    return a;
}

#define LDSM_X4(r0, r1, r2, r3, addr) \
    asm volatile("ldmatrix.sync.aligned.m8n8.x4.shared.b16 {%0,%1,%2,%3}, [%4];" \
                 : "=r"(r0), "=r"(r1), "=r"(r2), "=r"(r3) : "r"(addr))

#define MMA16816(c, a0, a1, a2, a3, b0, b1) \
    asm volatile("mma.sync.aligned.m16n8k16.row.col.f32.bf16.bf16.f32 " \
                 "{%0,%1,%2,%3}, {%4,%5,%6,%7}, {%8,%9}, {%0,%1,%2,%3};" \
                 : "+f"((c)[0]), "+f"((c)[1]), "+f"((c)[2]), "+f"((c)[3]) \
                 : "r"(a0), "r"(a1), "r"(a2), "r"(a3), "r"(b0), "r"(b1))

// monotone float->u32; key = (enc<<32)|idx : u64 '<' == lexicographic (val,idx)
__device__ __forceinline__ unsigned long long packkey(float v, int idx) {
    uint32_t u = __float_as_uint(v);
    u = (u >> 31) ? ~u : (u | 0x80000000u);
    return ((unsigned long long)u << 32) | (uint32_t)idx;
}
template<int NL>
__device__ __forceinline__ void insertU(unsigned long long l[NL], unsigned long long v) {
    if (v < l[NL - 1]) {
        l[NL - 1] = v;
#pragma unroll
        for (int s = NL - 1; s > 0; --s)
            if (l[s] < l[s - 1]) { unsigned long long t = l[s]; l[s] = l[s - 1]; l[s - 1] = t; }
    }
}
__device__ __forceinline__ bool lessp(float v, int i, float v2, int i2) {
    return (v < v2) || (v == v2 && i < i2);
}
__device__ __forceinline__ void insert5(float lv[KNN], int li[KNN], float v, int idx) {
    if (lessp(v, idx, lv[KNN - 1], li[KNN - 1])) {
        lv[KNN - 1] = v; li[KNN - 1] = idx;
#pragma unroll
        for (int s = KNN - 1; s > 0; --s) {
            if (lessp(lv[s], li[s], lv[s - 1], li[s - 1])) {
                float tv = lv[s]; lv[s] = lv[s - 1]; lv[s - 1] = tv;
                int   ti = li[s]; li[s] = li[s - 1]; li[s - 1] = ti;
            }
        }
    }
}

// ================= fused fp32->bf16 + squared row norms =================
__global__ void cvtsq_kernel(const float* __restrict__ X) {
    int warp = (blockIdx.x * blockDim.x + threadIdx.x) >> 5;
    int lane = threadIdx.x & 31;
    if (warp >= NPTS) return;
    const float2* src = (const float2*)(X + (size_t)warp * DIMX);
    __nv_bfloat162* dst = (__nv_bfloat162*)(g_xbf + (size_t)warp * DIMX);
    float s = 0.f;
#pragma unroll
    for (int t = 0; t < 4; ++t) {
        float2 v = src[lane + 32 * t];
        s = fmaf(v.x, v.x, fmaf(v.y, v.y, s));
        dst[lane + 32 * t] = __floats2bfloat162_rn(v.x, v.y);
    }
#pragma unroll
    for (int o = 16; o > 0; o >>= 1) s += __shfl_xor_sync(0xffffffffu, s, o);
    if (lane == 0) g_sq[warp] = s;
}

// ====== symmetric 64x64 tile-pair screen (R8 base), double-buffered stages ======
__global__ __launch_bounds__(256) void screen_pair_kernel() {
    // 2 stages x (A 8K + B 8K) = 32768 B; smC (64x65 fl = 16640 B) overlays after mainloop
    __shared__ __align__(16) uint8_t smRaw[32768];
    __shared__ float sqI[64], sqJ[64];
    float* smC = (float*)smRaw;

    const int tid = threadIdx.x;
    const int wid = tid >> 5;
    const int lane = tid & 31;
    const uint32_t sb = smem_u32(smRaw);

    // ---- linear pair index -> (ti, tj), ti <= tj ----
    const int k = blockIdx.x;
    int i = (int)(128.5f - sqrtf(128.5f * 128.5f - 2.0f * (float)k));
    if (i < 0) i = 0; if (i > NTILE - 1) i = NTILE - 1;
    while (i > 0 && (i * NTILE - i * (i - 1) / 2) > k) --i;
    while (((i + 1) * NTILE - (i + 1) * i / 2) <= k) ++i;
    const int ti = i;
    const int tj = i + (k - (i * NTILE - i * (i - 1) / 2));
    const int rbI = ti * 64, rbJ = tj * 64;

    if (tid < 64) { sqI[tid] = g_sq[rbI + tid]; sqJ[tid] = g_sq[rbJ + tid]; }

    // staging map: thread handles rows rr, rr+32; 16B-chunk cc of each 128B row
    const int rr = tid >> 3, cc = tid & 7;
    const uint32_t stOff0 = (uint32_t)rr * 128 + (((uint32_t)cc ^ (rr & 7)) << 4);
    const uint32_t stOff1 = (uint32_t)(rr + 32) * 128 + (((uint32_t)cc ^ ((rr + 32) & 7)) << 4);

    uint4 pa[2], pb[2];
#pragma unroll
    for (int it = 0; it < 2; ++it) {
        pa[it] = *(const uint4*)(g_xbf + (size_t)(rbI + rr + it * 32) * DIMX + cc * 8);
        pb[it] = *(const uint4*)(g_xbf + (size_t)(rbJ + rr + it * 32) * DIMX + cc * 8);
    }

    float c[4][4];
#pragma unroll
    for (int j = 0; j < 4; ++j)
#pragma unroll
        for (int q = 0; q < 4; ++q) c[j][q] = 0.f;

    // fragment addressing (stage-relative): warp (wid&3)=row group, (wid>>2)=col half
    const int rA = (wid & 3) * 16 + (lane & 15);
    const uint32_t aOff = (uint32_t)rA * 128;                 // within smA (stage + 0)
    const uint32_t aSw = (uint32_t)(rA & 7);
    const uint32_t aHi = (uint32_t)(lane >> 4);
    const int bLane = (lane & 7) + ((lane >> 4) << 3);
    const uint32_t bOff = 8192 + (uint32_t)bLane * 128;       // within smB (stage + 8192)
    const uint32_t bSw = (uint32_t)(lane & 7);
    const uint32_t bHi = (uint32_t)((lane >> 3) & 1);
    const uint32_t bBlk = (uint32_t)(wid >> 2) * 2;           // 16-col block base

    for (int kc = 0; kc < 4; ++kc) {
        const uint32_t stage = sb + (uint32_t)(kc & 1) * 16384;
        // write this chunk into its stage (WAR vs compute(kc-2) separated by sync(kc-1))
        *(uint4*)((uint8_t*)smRaw + (kc & 1) * 16384 + stOff0)        = pa[0];
        *(uint4*)((uint8_t*)smRaw + (kc & 1) * 16384 + stOff1)        = pa[1];
        *(uint4*)((uint8_t*)smRaw + (kc & 1) * 16384 + 8192 + stOff0) = pb[0];
        *(uint4*)((uint8_t*)smRaw + (kc & 1) * 16384 + 8192 + stOff1) = pb[1];
        __syncthreads();
        if (kc < 3) {
#pragma unroll
            for (int it = 0; it < 2; ++it) {
                pa[it] = *(const uint4*)(g_xbf + (size_t)(rbI + rr + it * 32) * DIMX + (kc + 1) * 64 + cc * 8);
                pb[it] = *(const uint4*)(g_xbf + (size_t)(rbJ + rr + it * 32) * DIMX + (kc + 1) * 64 + cc * 8);
            }
        }
#pragma unroll
        for (int ks = 0; ks < 4; ++ks) {
            uint32_t a0, a1, a2, a3;
            LDSM_X4(a0, a1, a2, a3, stage + aOff + ((((uint32_t)ks * 2 + aHi) ^ aSw) << 4));
            uint32_t ccB = (((uint32_t)ks * 2 + bHi) ^ bSw) << 4;
#pragma unroll
            for (int p = 0; p < 2; ++p) {
                uint32_t b0, b1, b2, b3;
                LDSM_X4(b0, b1, b2, b3, stage + bOff + (bBlk + p) * 2048 + ccB);
                MMA16816(c[2 * p],     a0, a1, a2, a3, b0, b1);
                MMA16816(c[2 * p + 1], a0, a1, a2, a3, b2, b3);
            }
        }
    }
    __syncthreads();   // all LDSM reads done before smC overlays stage 0

    // ---- stage C to smem (stride 65) ----
    {
        const int r0 = (wid & 3) * 16 + (lane >> 2), r1 = r0 + 8;
        const int cq = (wid >> 2) * 32 + 2 * (lane & 3);
#pragma unroll
        for (int j = 0; j < 4; ++j) {
            int col = cq + j * 8;
            smC[r0 * 65 + col]     = c[j][0];
            smC[r0 * 65 + col + 1] = c[j][1];
            smC[r1 * 65 + col]     = c[j][2];
            smC[r1 * 65 + col + 1] = c[j][3];
        }
    }
    __syncthreads();

    // ---- row side: 4 scanners per row, 16 cols each ----
    {
        const int r = tid >> 2, h = tid & 3;
        const int grow = rbI + r;
        unsigned long long l[PTOP];
#pragma unroll
        for (int s = 0; s < PTOP; ++s) l[s] = U64MAX;
#pragma unroll
        for (int s = 0; s < 16; ++s) {
            int cl = h * 16 + s;
            int idx = rbJ + cl;
            if (idx != grow)
                insertU<PTOP>(l, packkey(fmaf(-2.f, smC[r * 65 + cl], sqJ[cl]), idx));
        }
#pragma unroll
        for (int d = 1; d < 4; d <<= 1) {
            unsigned long long rv[PTOP];
#pragma unroll
            for (int s = 0; s < PTOP; ++s) rv[s] = __shfl_xor_sync(0xffffffffu, l[s], d);
            for (int s = 0; s < PTOP; ++s) {          // remote sorted: early break
                if (rv[s] >= l[PTOP - 1]) break;
                insertU<PTOP>(l, rv[s]);
            }
        }
        if (h == 0) {
            unsigned long long* dst = &g_p[((size_t)grow * NTILE + tj) * PTOP];
            ((ulonglong2*)dst)[0] = make_ulonglong2(l[0], l[1]);
            ((ulonglong2*)dst)[1] = make_ulonglong2(l[2], l[3]);
        }
    }

    // ---- col side (skip diagonal pair) ----
    if (ti != tj) {
        const int c2 = tid >> 2, h = tid & 3;
        const int grow = rbJ + c2;
        unsigned long long l[PTOP];
#pragma unroll
        for (int s = 0; s < PTOP; ++s) l[s] = U64MAX;
#pragma unroll
        for (int s = 0; s < 16; ++s) {
            int rl = h * 16 + s;
            insertU<PTOP>(l, packkey(fmaf(-2.f, smC[rl * 65 + c2], sqI[rl]), rbI + rl));
        }
#pragma unroll
        for (int d = 1; d < 4; d <<= 1) {
            unsigned long long rv[PTOP];
#pragma unroll
            for (int s = 0; s < PTOP; ++s) rv[s] = __shfl_xor_sync(0xffffffffu, l[s], d);
            for (int s = 0; s < PTOP; ++s) {
                if (rv[s] >= l[PTOP - 1]) break;
                insertU<PTOP>(l, rv[s]);
            }
        }
        if (h == 0) {
            unsigned long long* dst = &g_p[((size_t)grow * NTILE + ti) * PTOP];
            ((ulonglong2*)dst)[0] = make_ulonglong2(l[0], l[1]);
            ((ulonglong2*)dst)[1] = make_ulonglong2(l[2], l[3]);
        }
    }
}

// ======= merge: 2 warps per row (64 sorted lists each), early-break =======
__global__ __launch_bounds__(256) void merge_kernel() {
    __shared__ unsigned long long sh[8][GTOP];
    const int tid = threadIdx.x;
    const int wid = tid >> 5;
    const int lane = tid & 31;
    const int row = blockIdx.x * 4 + (wid >> 1);
    const int half = wid & 1;

    unsigned long long l[GTOP];
#pragma unroll
    for (int s = 0; s < GTOP; ++s) l[s] = U64MAX;
#pragma unroll
    for (int q = 0; q < 2; ++q) {
        int tile = half * 64 + q * 32 + lane;
        const unsigned long long* src = &g_p[((size_t)row * NTILE + tile) * PTOP];
        ulonglong2 v0 = ((const ulonglong2*)src)[0];
        ulonglong2 v1 = ((const ulonglong2*)src)[1];
        // v0.x < v0.y < v1.x < v1.y (written sorted): early break
        if (v0.x >= l[GTOP - 1]) continue;
        insertU<GTOP>(l, v0.x);
        if (v0.y >= l[GTOP - 1]) continue;
        insertU<GTOP>(l, v0.y);
        if (v1.x >= l[GTOP - 1]) continue;
        insertU<GTOP>(l, v1.x);
        if (v1.y < l[GTOP - 1]) insertU<GTOP>(l, v1.y);
    }
#pragma unroll
    for (int d = 1; d < 32; d <<= 1) {
        unsigned long long rv[GTOP];
#pragma unroll
        for (int s = 0; s < GTOP; ++s) rv[s] = __shfl_xor_sync(0xffffffffu, l[s], d);
        for (int s = 0; s < GTOP; ++s) {     // remote sorted ascending: early break
            if (rv[s] >= l[GTOP - 1]) break;
            insertU<GTOP>(l, rv[s]);
        }
    }
    if (lane == 0) {
#pragma unroll
        for (int s = 0; s < GTOP; ++s) sh[wid][s] = l[s];
    }
    __syncthreads();
    if (half == 0 && lane == 0) {
        for (int s = 0; s < GTOP; ++s) {
            unsigned long long rv = sh[wid + 1][s];
            if (rv >= l[GTOP - 1]) break;
            insertU<GTOP>(l, rv);
        }
#pragma unroll
        for (int s = 0; s < GTOP; ++s) g_cand[row][s] = (int)(uint32_t)(l[s] & 0xffffffffu);
    }
}

// ===== fused: exact fp32 re-rank -> lid_X -> z-distances -> lid_Z -> block sum =====
__global__ __launch_bounds__(256) void rerank_z_kernel(const float* __restrict__ X,
                                                       const float* __restrict__ Z) {
    __shared__ float bsum[8];
    const int warp = (blockIdx.x * blockDim.x + threadIdx.x) >> 5;
    const int lane = threadIdx.x & 31;
    const int wid = threadIdx.x >> 5;
    const int row = warp;

    float xi[8];
#pragma unroll
    for (int t = 0; t < 8; ++t) xi[t] = X[(size_t)row * DIMX + lane + 32 * t];
    const float sqr = g_sq[row];

    float lv[KNN]; int li[KNN];
#pragma unroll
    for (int s = 0; s < KNN; ++s) { lv[s] = 3.4e38f; li[s] = 0x7fffffff; }

#pragma unroll
    for (int s = 0; s < GTOP; ++s) {
        int j = g_cand[row][s];
        const float* xr = X + (size_t)j * DIMX;
        float d = 0.f;
#pragma unroll
        for (int t = 0; t < 8; ++t) d = fmaf(xi[t], xr[lane + 32 * t], d);
#pragma unroll
        for (int o = 16; o > 0; o >>= 1) d += __shfl_xor_sync(0xffffffffu, d, o);
        insert5(lv, li, sqr + g_sq[j] - 2.f * d, j);
    }

    float lidX;
    {
        float vK = sqrtf(fmaxf(lv[KNN - 1], 0.f)) + EPSF;
        float lgK = log10f(vK);
        lidX = 0.f;
#pragma unroll
        for (int s = 0; s < KNN; ++s)
            lidX += lgK - log10f(sqrtf(fmaxf(lv[s], 0.f)) + EPSF);
    }

    float z0 = Z[(size_t)row * DIMZ + lane];
    float z1 = Z[(size_t)row * DIMZ + 32 + lane];
    float e[KNN];
#pragma unroll
    for (int s = 0; s < KNN; ++s) {
        int m = li[s];
        float d0 = z0 - Z[(size_t)m * DIMZ + lane];
        float d1 = z1 - Z[(size_t)m * DIMZ + 32 + lane];
        float ss = fmaf(d0, d0, d1 * d1);
#pragma unroll
        for (int o = 16; o > 0; o >>= 1) ss += __shfl_xor_sync(0xffffffffu, ss, o);
        e[s] = sqrtf(ss) + EPSF;
    }
    float lgK = log10f(e[KNN - 1]);
    float lidZ = 0.f;
#pragma unroll
    for (int s = 0; s < KNN; ++s) lidZ += lgK - log10f(e[s]);
    float d = lidX - lidZ;

    if (lane == 0) bsum[wid] = d * d;
    __syncthreads();
    if (threadIdx.x == 0) {
        float s = 0.f;
#pragma unroll
        for (int w = 0; w < 8; ++w) s += bsum[w];
        g_bsum[blockIdx.x] = s;
    }
}

// ================= final deterministic reduction =================
__global__ void final_reduce(float* __restrict__ out) {
    __shared__ float sh[256];
    int t = threadIdx.x;
    float s = g_bsum[t] + g_bsum[t + 256] + g_bsum[t + 512] + g_bsum[t + 768];
    sh[t] = s;
    __syncthreads();
    for (int o = 128; o > 0; o >>= 1) {
        if (t < o) sh[t] += sh[t + o];
        __syncthreads();
    }
    if (t == 0) out[0] = sh[0] * (1.f / ((float)NPTS * KNN * 10.f));
}

extern "C" void kernel_launch(void* const* d_in, const int* in_sizes, int n_in,
                              void* d_out, int out_size) {
    const float* X = (const float*)d_in[0];   // (8192, 256)
    const float* Z = (const float*)d_in[1];   // (8192, 64)
    float* out = (float*)d_out;

    cvtsq_kernel<<<NPTS / 8, 256>>>(X);
    screen_pair_kernel<<<NPAIRS, 256>>>();
    merge_kernel<<<NPTS / 4, 256>>>();
    rerank_z_kernel<<<NPTS / 8, 256>>>(X, Z);
    final_reduce<<<1, 256>>>(out);
}

// round 12
// speedup vs baseline: 1.7165x; 1.0087x over previous
#include <cuda_runtime.h>
#include <cuda_bf16.h>
#include <cstdint>

#define NPTS 8192
#define DIMX 256
#define DIMZ 64
#define KNN  5
#define EPSF 1e-7f

#define NTILE 128                          // 8192 / 64 row-tiles
#define NPAIRS (NTILE * (NTILE + 1) / 2)   // 8256
#define PTOP 4
#define GTOP 8
#define U64MAX 0xFFFFFFFFFFFFFFFFull

// ---- scratch ----
__device__ float g_sq[NPTS];
__device__ __nv_bfloat16 g_xbf[NPTS * DIMX];
__device__ unsigned long long g_p[(size_t)NPTS * NTILE * PTOP];   // 33.5 MB
__device__ int   g_cand[NPTS][GTOP];
__device__ float g_bsum[1024];

__device__ __forceinline__ uint32_t smem_u32(const void* p) {
    uint32_t a;
    asm("{ .reg .u64 t; cvta.to.shared.u64 t, %1; cvt.u32.u64 %0, t; }" : "=r"(a) : "l"(p));
    return a;
}

#define LDSM_X4(r0, r1, r2, r3, addr) \
    asm volatile("ldmatrix.sync.aligned.m8n8.x4.shared.b16 {%0,%1,%2,%3}, [%4];" \
                 : "=r"(r0), "=r"(r1), "=r"(r2), "=r"(r3) : "r"(addr))

#define MMA16816(c, a0, a1, a2, a3, b0, b1) \
    asm volatile("mma.sync.aligned.m16n8k16.row.col.f32.bf16.bf16.f32 " \
                 "{%0,%1,%2,%3}, {%4,%5,%6,%7}, {%8,%9}, {%0,%1,%2,%3};" \
                 : "+f"((c)[0]), "+f"((c)[1]), "+f"((c)[2]), "+f"((c)[3]) \
                 : "r"(a0), "r"(a1), "r"(a2), "r"(a3), "r"(b0), "r"(b1))

// monotone float->u32; key = (enc<<32)|idx : u64 '<' == lexicographic (val,idx)
__device__ __forceinline__ unsigned long long packkey(float v, int idx) {
    uint32_t u = __float_as_uint(v);
    u = (u >> 31) ? ~u : (u | 0x80000000u);
    return ((unsigned long long)u << 32) | (uint32_t)idx;
}
template<int NL>
__device__ __forceinline__ void insertU(unsigned long long l[NL], unsigned long long v) {
    if (v < l[NL - 1]) {
        l[NL - 1] = v;
#pragma unroll
        for (int s = NL - 1; s > 0; --s)
            if (l[s] < l[s - 1]) { unsigned long long t = l[s]; l[s] = l[s - 1]; l[s - 1] = t; }
    }
}
__device__ __forceinline__ bool lessp(float v, int i, float v2, int i2) {
    return (v < v2) || (v == v2 && i < i2);
}
__device__ __forceinline__ void insert5(float lv[KNN], int li[KNN], float v, int idx) {
    if (lessp(v, idx, lv[KNN - 1], li[KNN - 1])) {
        lv[KNN - 1] = v; li[KNN - 1] = idx;
#pragma unroll
        for (int s = KNN - 1; s > 0; --s) {
            if (lessp(lv[s], li[s], lv[s - 1], li[s - 1])) {
                float tv = lv[s]; lv[s] = lv[s - 1]; lv[s - 1] = tv;
                int   ti = li[s]; li[s] = li[s - 1]; li[s - 1] = ti;
            }
        }
    }
}

// ================= fused fp32->bf16 + squared row norms =================
__global__ void cvtsq_kernel(const float* __restrict__ X) {
    int warp = (blockIdx.x * blockDim.x + threadIdx.x) >> 5;
    int lane = threadIdx.x & 31;
    if (warp >= NPTS) return;
    const float2* src = (const float2*)(X + (size_t)warp * DIMX);
    __nv_bfloat162* dst = (__nv_bfloat162*)(g_xbf + (size_t)warp * DIMX);
    float s = 0.f;
#pragma unroll
    for (int t = 0; t < 4; ++t) {
        float2 v = src[lane + 32 * t];
        s = fmaf(v.x, v.x, fmaf(v.y, v.y, s));
        dst[lane + 32 * t] = __floats2bfloat162_rn(v.x, v.y);
    }
#pragma unroll
    for (int o = 16; o > 0; o >>= 1) s += __shfl_xor_sync(0xffffffffu, s, o);
    if (lane == 0) g_sq[warp] = s;
}

// ====== symmetric 64x64 tile-pair screen (R8-proven version, unchanged) ======
__global__ __launch_bounds__(256) void screen_pair_kernel() {
    __shared__ __align__(16) uint8_t smA[64 * 128];   // 64 rows x 64 bf16 k-chunk
    __shared__ __align__(16) uint8_t smB[64 * 128];
    __shared__ float smC[64 * 65];
    __shared__ float sqI[64], sqJ[64];

    const int tid = threadIdx.x;
    const int wid = tid >> 5;
    const int lane = tid & 31;

    // ---- linear pair index -> (ti, tj), ti <= tj ----
    const int k = blockIdx.x;
    int i = (int)(128.5f - sqrtf(128.5f * 128.5f - 2.0f * (float)k));
    if (i < 0) i = 0; if (i > NTILE - 1) i = NTILE - 1;
    while (i > 0 && (i * NTILE - i * (i - 1) / 2) > k) --i;
    while (((i + 1) * NTILE - (i + 1) * i / 2) <= k) ++i;
    const int ti = i;
    const int tj = i + (k - (i * NTILE - i * (i - 1) / 2));
    const int rbI = ti * 64, rbJ = tj * 64;

    if (tid < 64) { sqI[tid] = g_sq[rbI + tid]; sqJ[tid] = g_sq[rbJ + tid]; }

    // staging map: 512 16B-chunks per tile-chunk; thread handles chunk tid and tid+256
    const int rr = tid >> 3, cc = tid & 7;   // r in 0..31, +32 for second

    uint4 pa[2], pb[2];
#pragma unroll
    for (int it = 0; it < 2; ++it) {
        pa[it] = *(const uint4*)(g_xbf + (size_t)(rbI + rr + it * 32) * DIMX + cc * 8);
        pb[it] = *(const uint4*)(g_xbf + (size_t)(rbJ + rr + it * 32) * DIMX + cc * 8);
    }

    float c[4][4];
#pragma unroll
    for (int j = 0; j < 4; ++j)
#pragma unroll
        for (int q = 0; q < 4; ++q) c[j][q] = 0.f;

    // fragment addressing: warp (wid&3) -> row group, (wid>>2) -> col half
    const int rA = (wid & 3) * 16 + (lane & 15);
    const uint32_t aRowB = smem_u32(smA) + (uint32_t)rA * 128;
    const uint32_t aSw = (uint32_t)(rA & 7);
    const uint32_t aHi = (uint32_t)(lane >> 4);
    const int bLane = (lane & 7) + ((lane >> 4) << 3);
    const uint32_t bRowB = smem_u32(smB) + (uint32_t)bLane * 128;
    const uint32_t bSw = (uint32_t)(lane & 7);
    const uint32_t bHi = (uint32_t)((lane >> 3) & 1);
    const uint32_t bBlk = (uint32_t)(wid >> 2) * 2;   // 16-col block base

    for (int kc = 0; kc < 4; ++kc) {
        __syncthreads();
#pragma unroll
        for (int it = 0; it < 2; ++it) {
            int r = rr + it * 32;
            *(uint4*)(smA + r * 128 + (((uint32_t)cc ^ (r & 7)) << 4)) = pa[it];
            *(uint4*)(smB + r * 128 + (((uint32_t)cc ^ (r & 7)) << 4)) = pb[it];
        }
        __syncthreads();
        if (kc < 3) {
#pragma unroll
            for (int it = 0; it < 2; ++it) {
                pa[it] = *(const uint4*)(g_xbf + (size_t)(rbI + rr + it * 32) * DIMX + (kc + 1) * 64 + cc * 8);
                pb[it] = *(const uint4*)(g_xbf + (size_t)(rbJ + rr + it * 32) * DIMX + (kc + 1) * 64 + cc * 8);
            }
        }
#pragma unroll
        for (int ks = 0; ks < 4; ++ks) {
            uint32_t a0, a1, a2, a3;
            LDSM_X4(a0, a1, a2, a3, aRowB + ((((uint32_t)ks * 2 + aHi) ^ aSw) << 4));
            uint32_t ccB = (((uint32_t)ks * 2 + bHi) ^ bSw) << 4;
#pragma unroll
            for (int p = 0; p < 2; ++p) {
                uint32_t b0, b1, b2, b3;
                LDSM_X4(b0, b1, b2, b3, bRowB + (bBlk + p) * 2048 + ccB);
                MMA16816(c[2 * p],     a0, a1, a2, a3, b0, b1);
                MMA16816(c[2 * p + 1], a0, a1, a2, a3, b2, b3);
            }
        }
    }

    // ---- stage C to smem (stride 65) ----
    {
        const int r0 = (wid & 3) * 16 + (lane >> 2), r1 = r0 + 8;
        const int cq = (wid >> 2) * 32 + 2 * (lane & 3);
#pragma unroll
        for (int j = 0; j < 4; ++j) {
            int col = cq + j * 8;
            smC[r0 * 65 + col]     = c[j][0];
            smC[r0 * 65 + col + 1] = c[j][1];
            smC[r1 * 65 + col]     = c[j][2];
            smC[r1 * 65 + col + 1] = c[j][3];
        }
    }
    __syncthreads();

    // ---- row side: 4 scanners per row, 16 cols each ----
    {
        const int r = tid >> 2, h = tid & 3;
        const int grow = rbI + r;
        unsigned long long l[PTOP];
#pragma unroll
        for (int s = 0; s < PTOP; ++s) l[s] = U64MAX;
#pragma unroll
        for (int s = 0; s < 16; ++s) {
            int cl = h * 16 + s;
            int idx = rbJ + cl;
            if (idx != grow)
                insertU<PTOP>(l, packkey(fmaf(-2.f, smC[r * 65 + cl], sqJ[cl]), idx));
        }
#pragma unroll
        for (int d = 1; d < 4; d <<= 1) {
            unsigned long long rv[PTOP];
#pragma unroll
            for (int s = 0; s < PTOP; ++s) rv[s] = __shfl_xor_sync(0xffffffffu, l[s], d);
            for (int s = 0; s < PTOP; ++s) {          // remote sorted: early break
                if (rv[s] >= l[PTOP - 1]) break;
                insertU<PTOP>(l, rv[s]);
            }
        }
        if (h == 0) {
            unsigned long long* dst = &g_p[((size_t)grow * NTILE + tj) * PTOP];
            ((ulonglong2*)dst)[0] = make_ulonglong2(l[0], l[1]);
            ((ulonglong2*)dst)[1] = make_ulonglong2(l[2], l[3]);
        }
    }

    // ---- col side (skip diagonal pair) ----
    if (ti != tj) {
        const int c2 = tid >> 2, h = tid & 3;
        const int grow = rbJ + c2;
        unsigned long long l[PTOP];
#pragma unroll
        for (int s = 0; s < PTOP; ++s) l[s] = U64MAX;
#pragma unroll
        for (int s = 0; s < 16; ++s) {
            int rl = h * 16 + s;
            insertU<PTOP>(l, packkey(fmaf(-2.f, smC[rl * 65 + c2], sqI[rl]), rbI + rl));
        }
#pragma unroll
        for (int d = 1; d < 4; d <<= 1) {
            unsigned long long rv[PTOP];
#pragma unroll
            for (int s = 0; s < PTOP; ++s) rv[s] = __shfl_xor_sync(0xffffffffu, l[s], d);
            for (int s = 0; s < PTOP; ++s) {
                if (rv[s] >= l[PTOP - 1]) break;
                insertU<PTOP>(l, rv[s]);
            }
        }
        if (h == 0) {
            unsigned long long* dst = &g_p[((size_t)grow * NTILE + ti) * PTOP];
            ((ulonglong2*)dst)[0] = make_ulonglong2(l[0], l[1]);
            ((ulonglong2*)dst)[1] = make_ulonglong2(l[2], l[3]);
        }
    }
}

// ======= merge: 2 warps per row (64 sorted lists each), early-break =======
__global__ __launch_bounds__(256) void merge_kernel() {
    __shared__ unsigned long long sh[8][GTOP];
    const int tid = threadIdx.x;
    const int wid = tid >> 5;
    const int lane = tid & 31;
    const int row = blockIdx.x * 4 + (wid >> 1);
    const int half = wid & 1;

    unsigned long long l[GTOP];
#pragma unroll
    for (int s = 0; s < GTOP; ++s) l[s] = U64MAX;
#pragma unroll
    for (int q = 0; q < 2; ++q) {
        int tile = half * 64 + q * 32 + lane;
        const unsigned long long* src = &g_p[((size_t)row * NTILE + tile) * PTOP];
        ulonglong2 v0 = ((const ulonglong2*)src)[0];
        ulonglong2 v1 = ((const ulonglong2*)src)[1];
        // v0.x < v0.y < v1.x < v1.y (written sorted): early break
        if (v0.x >= l[GTOP - 1]) continue;
        insertU<GTOP>(l, v0.x);
        if (v0.y >= l[GTOP - 1]) continue;
        insertU<GTOP>(l, v0.y);
        if (v1.x >= l[GTOP - 1]) continue;
        insertU<GTOP>(l, v1.x);
        if (v1.y < l[GTOP - 1]) insertU<GTOP>(l, v1.y);
    }
#pragma unroll
    for (int d = 1; d < 32; d <<= 1) {
        unsigned long long rv[GTOP];
#pragma unroll
        for (int s = 0; s < GTOP; ++s) rv[s] = __shfl_xor_sync(0xffffffffu, l[s], d);
        for (int s = 0; s < GTOP; ++s) {     // remote sorted ascending: early break
            if (rv[s] >= l[GTOP - 1]) break;
            insertU<GTOP>(l, rv[s]);
        }
    }
    if (lane == 0) {
#pragma unroll
        for (int s = 0; s < GTOP; ++s) sh[wid][s] = l[s];
    }
    __syncthreads();
    if (half == 0 && lane == 0) {
        for (int s = 0; s < GTOP; ++s) {
            unsigned long long rv = sh[wid + 1][s];
            if (rv >= l[GTOP - 1]) break;
            insertU<GTOP>(l, rv);
        }
#pragma unroll
        for (int s = 0; s < GTOP; ++s) g_cand[row][s] = (int)(uint32_t)(l[s] & 0xffffffffu);
    }
}

// ===== fused: exact fp32 re-rank -> lid_X -> z-distances -> lid_Z -> block sum =====
__global__ __launch_bounds__(256) void rerank_z_kernel(const float* __restrict__ X,
                                                       const float* __restrict__ Z) {
    __shared__ float bsum[8];
    const int warp = (blockIdx.x * blockDim.x + threadIdx.x) >> 5;
    const int lane = threadIdx.x & 31;
    const int wid = threadIdx.x >> 5;
    const int row = warp;

    float xi[8];
#pragma unroll
    for (int t = 0; t < 8; ++t) xi[t] = X[(size_t)row * DIMX + lane + 32 * t];
    const float sqr = g_sq[row];

    float lv[KNN]; int li[KNN];
#pragma unroll
    for (int s = 0; s < KNN; ++s) { lv[s] = 3.4e38f; li[s] = 0x7fffffff; }

#pragma unroll
    for (int s = 0; s < GTOP; ++s) {
        int j = g_cand[row][s];
        const float* xr = X + (size_t)j * DIMX;
        float d = 0.f;
#pragma unroll
        for (int t = 0; t < 8; ++t) d = fmaf(xi[t], xr[lane + 32 * t], d);
#pragma unroll
        for (int o = 16; o > 0; o >>= 1) d += __shfl_xor_sync(0xffffffffu, d, o);
        insert5(lv, li, sqr + g_sq[j] - 2.f * d, j);
    }

    float lidX;
    {
        float vK = sqrtf(fmaxf(lv[KNN - 1], 0.f)) + EPSF;
        float lgK = log10f(vK);
        lidX = 0.f;
#pragma unroll
        for (int s = 0; s < KNN; ++s)
            lidX += lgK - log10f(sqrtf(fmaxf(lv[s], 0.f)) + EPSF);
    }

    float z0 = Z[(size_t)row * DIMZ + lane];
    float z1 = Z[(size_t)row * DIMZ + 32 + lane];
    float e[KNN];
#pragma unroll
    for (int s = 0; s < KNN; ++s) {
        int m = li[s];
        float d0 = z0 - Z[(size_t)m * DIMZ + lane];
        float d1 = z1 - Z[(size_t)m * DIMZ + 32 + lane];
        float ss = fmaf(d0, d0, d1 * d1);
#pragma unroll
        for (int o = 16; o > 0; o >>= 1) ss += __shfl_xor_sync(0xffffffffu, ss, o);
        e[s] = sqrtf(ss) + EPSF;
    }
    float lgK = log10f(e[KNN - 1]);
    float lidZ = 0.f;
#pragma unroll
    for (int s = 0; s < KNN; ++s) lidZ += lgK - log10f(e[s]);
    float d = lidX - lidZ;

    if (lane == 0) bsum[wid] = d * d;
    __syncthreads();
    if (threadIdx.x == 0) {
        float s = 0.f;
#pragma unroll
        for (int w = 0; w < 8; ++w) s += bsum[w];
        g_bsum[blockIdx.x] = s;
    }
}

// ================= final deterministic reduction =================
__global__ void final_reduce(float* __restrict__ out) {
    __shared__ float sh[256];
    int t = threadIdx.x;
    float s = g_bsum[t] + g_bsum[t + 256] + g_bsum[t + 512] + g_bsum[t + 768];
    sh[t] = s;
    __syncthreads();
    for (int o = 128; o > 0; o >>= 1) {
        if (t < o) sh[t] += sh[t + o];
        __syncthreads();
    }
    if (t == 0) out[0] = sh[0] * (1.f / ((float)NPTS * KNN * 10.f));
}

extern "C" void kernel_launch(void* const* d_in, const int* in_sizes, int n_in,
                              void* d_out, int out_size) {
    const float* X = (const float*)d_in[0];   // (8192, 256)
    const float* Z = (const float*)d_in[1];   // (8192, 64)
    float* out = (float*)d_out;

    cvtsq_kernel<<<NPTS / 8, 256>>>(X);
    screen_pair_kernel<<<NPAIRS, 256>>>();
    merge_kernel<<<NPTS / 4, 256>>>();
    rerank_z_kernel<<<NPTS / 8, 256>>>(X, Z);
    final_reduce<<<1, 256>>>(out);
}

// round 13
// speedup vs baseline: 2.6725x; 1.5569x over previous
#include <cuda_runtime.h>
#include <cuda_bf16.h>
#include <cstdint>

#define NPTS 8192
#define DIMX 256
#define DIMZ 64
#define KNN  5
#define EPSF 1e-7f

#define NTILE 128                          // 8192 / 64 row-tiles
#define NPAIRS (NTILE * (NTILE + 1) / 2)   // 8256
#define PTOP 4
#define GTOP 8
#define U32MAX 0xFFFFFFFFu
#define IDXMASK 0x1FFFu                    // 13 bits: idx < 8192

// ---- scratch ----
__device__ float g_sq[NPTS];
__device__ __nv_bfloat16 g_xbf[NPTS * DIMX];
__device__ uint4 g_p[(size_t)NPTS * NTILE];   // 16.8 MB: 4 packed u32 keys per (row,tile)
__device__ int   g_cand[NPTS][GTOP];
__device__ float g_bsum[1024];

__device__ __forceinline__ uint32_t smem_u32(const void* p) {
    uint32_t a;
    asm("{ .reg .u64 t; cvta.to.shared.u64 t, %1; cvt.u32.u64 %0, t; }" : "=r"(a) : "l"(p));
    return a;
}

#define LDSM_X4(r0, r1, r2, r3, addr) \
    asm volatile("ldmatrix.sync.aligned.m8n8.x4.shared.b16 {%0,%1,%2,%3}, [%4];" \
                 : "=r"(r0), "=r"(r1), "=r"(r2), "=r"(r3) : "r"(addr))

#define MMA16816(c, a0, a1, a2, a3, b0, b1) \
    asm volatile("mma.sync.aligned.m16n8k16.row.col.f32.bf16.bf16.f32 " \
                 "{%0,%1,%2,%3}, {%4,%5,%6,%7}, {%8,%9}, {%0,%1,%2,%3};" \
                 : "+f"((c)[0]), "+f"((c)[1]), "+f"((c)[2]), "+f"((c)[3]) \
                 : "r"(a0), "r"(a1), "r"(a2), "r"(a3), "r"(b0), "r"(b1))

// monotone float->u32, top 19 bits kept; low 13 bits = idx.
// u32 '<' == (quantized value, idx) lexicographic.
__device__ __forceinline__ uint32_t packkey32(float v, int idx) {
    uint32_t u = __float_as_uint(v);
    u = (u >> 31) ? ~u : (u | 0x80000000u);
    return (u & ~IDXMASK) | (uint32_t)idx;
}
template<int NL>
__device__ __forceinline__ void insertK(uint32_t l[NL], uint32_t v) {
    if (v < l[NL - 1]) {
        l[NL - 1] = v;
#pragma unroll
        for (int s = NL - 1; s > 0; --s)
            if (l[s] < l[s - 1]) { uint32_t t = l[s]; l[s] = l[s - 1]; l[s - 1] = t; }
    }
}
__device__ __forceinline__ bool lessp(float v, int i, float v2, int i2) {
    return (v < v2) || (v == v2 && i < i2);
}
__device__ __forceinline__ void insert5(float lv[KNN], int li[KNN], float v, int idx) {
    if (lessp(v, idx, lv[KNN - 1], li[KNN - 1])) {
        lv[KNN - 1] = v; li[KNN - 1] = idx;
#pragma unroll
        for (int s = KNN - 1; s > 0; --s) {
            if (lessp(lv[s], li[s], lv[s - 1], li[s - 1])) {
                float tv = lv[s]; lv[s] = lv[s - 1]; lv[s - 1] = tv;
                int   ti = li[s]; li[s] = li[s - 1]; li[s - 1] = ti;
            }
        }
    }
}

// ================= fused fp32->bf16 + squared row norms =================
__global__ void cvtsq_kernel(const float* __restrict__ X) {
    int warp = (blockIdx.x * blockDim.x + threadIdx.x) >> 5;
    int lane = threadIdx.x & 31;
    if (warp >= NPTS) return;
    const float2* src = (const float2*)(X + (size_t)warp * DIMX);
    __nv_bfloat162* dst = (__nv_bfloat162*)(g_xbf + (size_t)warp * DIMX);
    float s = 0.f;
#pragma unroll
    for (int t = 0; t < 4; ++t) {
        float2 v = src[lane + 32 * t];
        s = fmaf(v.x, v.x, fmaf(v.y, v.y, s));
        dst[lane + 32 * t] = __floats2bfloat162_rn(v.x, v.y);
    }
#pragma unroll
    for (int o = 16; o > 0; o >>= 1) s += __shfl_xor_sync(0xffffffffu, s, o);
    if (lane == 0) g_sq[warp] = s;
}

// ====== symmetric 64x64 tile-pair screen (R8 mainloop; u32-key epilogue) ======
__global__ __launch_bounds__(256) void screen_pair_kernel() {
    __shared__ __align__(16) uint8_t smA[64 * 128];   // 64 rows x 64 bf16 k-chunk
    __shared__ __align__(16) uint8_t smB[64 * 128];
    __shared__ float smC[64 * 65];
    __shared__ float sqI[64], sqJ[64];

    const int tid = threadIdx.x;
    const int wid = tid >> 5;
    const int lane = tid & 31;

    // ---- linear pair index -> (ti, tj), ti <= tj ----
    const int k = blockIdx.x;
    int i = (int)(128.5f - sqrtf(128.5f * 128.5f - 2.0f * (float)k));
    if (i < 0) i = 0; if (i > NTILE - 1) i = NTILE - 1;
    while (i > 0 && (i * NTILE - i * (i - 1) / 2) > k) --i;
    while (((i + 1) * NTILE - (i + 1) * i / 2) <= k) ++i;
    const int ti = i;
    const int tj = i + (k - (i * NTILE - i * (i - 1) / 2));
    const int rbI = ti * 64, rbJ = tj * 64;

    if (tid < 64) { sqI[tid] = g_sq[rbI + tid]; sqJ[tid] = g_sq[rbJ + tid]; }

    // staging map: 512 16B-chunks per tile-chunk; thread handles chunk tid and tid+256
    const int rr = tid >> 3, cc = tid & 7;   // r in 0..31, +32 for second

    uint4 pa[2], pb[2];
#pragma unroll
    for (int it = 0; it < 2; ++it) {
        pa[it] = *(const uint4*)(g_xbf + (size_t)(rbI + rr + it * 32) * DIMX + cc * 8);
        pb[it] = *(const uint4*)(g_xbf + (size_t)(rbJ + rr + it * 32) * DIMX + cc * 8);
    }

    float c[4][4];
#pragma unroll
    for (int j = 0; j < 4; ++j)
#pragma unroll
        for (int q = 0; q < 4; ++q) c[j][q] = 0.f;

    // fragment addressing: warp (wid&3) -> row group, (wid>>2) -> col half
    const int rA = (wid & 3) * 16 + (lane & 15);
    const uint32_t aRowB = smem_u32(smA) + (uint32_t)rA * 128;
    const uint32_t aSw = (uint32_t)(rA & 7);
    const uint32_t aHi = (uint32_t)(lane >> 4);
    const int bLane = (lane & 7) + ((lane >> 4) << 3);
    const uint32_t bRowB = smem_u32(smB) + (uint32_t)bLane * 128;
    const uint32_t bSw = (uint32_t)(lane & 7);
    const uint32_t bHi = (uint32_t)((lane >> 3) & 1);
    const uint32_t bBlk = (uint32_t)(wid >> 2) * 2;   // 16-col block base

    for (int kc = 0; kc < 4; ++kc) {
        __syncthreads();
#pragma unroll
        for (int it = 0; it < 2; ++it) {
            int r = rr + it * 32;
            *(uint4*)(smA + r * 128 + (((uint32_t)cc ^ (r & 7)) << 4)) = pa[it];
            *(uint4*)(smB + r * 128 + (((uint32_t)cc ^ (r & 7)) << 4)) = pb[it];
        }
        __syncthreads();
        if (kc < 3) {
#pragma unroll
            for (int it = 0; it < 2; ++it) {
                pa[it] = *(const uint4*)(g_xbf + (size_t)(rbI + rr + it * 32) * DIMX + (kc + 1) * 64 + cc * 8);
                pb[it] = *(const uint4*)(g_xbf + (size_t)(rbJ + rr + it * 32) * DIMX + (kc + 1) * 64 + cc * 8);
            }
        }
#pragma unroll
        for (int ks = 0; ks < 4; ++ks) {
            uint32_t a0, a1, a2, a3;
            LDSM_X4(a0, a1, a2, a3, aRowB + ((((uint32_t)ks * 2 + aHi) ^ aSw) << 4));
            uint32_t ccB = (((uint32_t)ks * 2 + bHi) ^ bSw) << 4;
#pragma unroll
            for (int p = 0; p < 2; ++p) {
                uint32_t b0, b1, b2, b3;
                LDSM_X4(b0, b1, b2, b3, bRowB + (bBlk + p) * 2048 + ccB);
                MMA16816(c[2 * p],     a0, a1, a2, a3, b0, b1);
                MMA16816(c[2 * p + 1], a0, a1, a2, a3, b2, b3);
            }
        }
    }

    // ---- stage C to smem (stride 65) ----
    {
        const int r0 = (wid & 3) * 16 + (lane >> 2), r1 = r0 + 8;
        const int cq = (wid >> 2) * 32 + 2 * (lane & 3);
#pragma unroll
        for (int j = 0; j < 4; ++j) {
            int col = cq + j * 8;
            smC[r0 * 65 + col]     = c[j][0];
            smC[r0 * 65 + col + 1] = c[j][1];
            smC[r1 * 65 + col]     = c[j][2];
            smC[r1 * 65 + col + 1] = c[j][3];
        }
    }
    __syncthreads();

    // ---- row side: 4 scanners per row, 16 cols each (u32 keys) ----
    {
        const int r = tid >> 2, h = tid & 3;
        const int grow = rbI + r;
        uint32_t l[PTOP];
#pragma unroll
        for (int s = 0; s < PTOP; ++s) l[s] = U32MAX;
#pragma unroll
        for (int s = 0; s < 16; ++s) {
            int cl = h * 16 + s;
            int idx = rbJ + cl;
            if (idx != grow)
                insertK<PTOP>(l, packkey32(fmaf(-2.f, smC[r * 65 + cl], sqJ[cl]), idx));
        }
#pragma unroll
        for (int d = 1; d < 4; d <<= 1) {
            uint32_t rv[PTOP];
#pragma unroll
            for (int s = 0; s < PTOP; ++s) rv[s] = __shfl_xor_sync(0xffffffffu, l[s], d);
            for (int s = 0; s < PTOP; ++s) {          // remote sorted: early break
                if (rv[s] >= l[PTOP - 1]) break;
                insertK<PTOP>(l, rv[s]);
            }
        }
        if (h == 0)
            g_p[(size_t)grow * NTILE + tj] = make_uint4(l[0], l[1], l[2], l[3]);
    }

    // ---- col side (skip diagonal pair) ----
    if (ti != tj) {
        const int c2 = tid >> 2, h = tid & 3;
        const int grow = rbJ + c2;
        uint32_t l[PTOP];
#pragma unroll
        for (int s = 0; s < PTOP; ++s) l[s] = U32MAX;
#pragma unroll
        for (int s = 0; s < 16; ++s) {
            int rl = h * 16 + s;
            insertK<PTOP>(l, packkey32(fmaf(-2.f, smC[rl * 65 + c2], sqI[rl]), rbI + rl));
        }
#pragma unroll
        for (int d = 1; d < 4; d <<= 1) {
            uint32_t rv[PTOP];
#pragma unroll
            for (int s = 0; s < PTOP; ++s) rv[s] = __shfl_xor_sync(0xffffffffu, l[s], d);
            for (int s = 0; s < PTOP; ++s) {
                if (rv[s] >= l[PTOP - 1]) break;
                insertK<PTOP>(l, rv[s]);
            }
        }
        if (h == 0)
            g_p[(size_t)grow * NTILE + ti] = make_uint4(l[0], l[1], l[2], l[3]);
    }
}

// ======= merge (R8 shape: warp per row), u32 keys, early-break =======
__global__ void merge_kernel() {
    int warp = (blockIdx.x * blockDim.x + threadIdx.x) >> 5;
    int lane = threadIdx.x & 31;
    if (warp >= NPTS) return;
    uint32_t l[GTOP];
#pragma unroll
    for (int s = 0; s < GTOP; ++s) l[s] = U32MAX;
#pragma unroll
    for (int q = 0; q < 4; ++q) {
        uint4 v = g_p[(size_t)warp * NTILE + lane + q * 32];
        // v.x < v.y < v.z < v.w (written sorted): early break
        if (v.x >= l[GTOP - 1]) continue;
        insertK<GTOP>(l, v.x);
        if (v.y >= l[GTOP - 1]) continue;
        insertK<GTOP>(l, v.y);
        if (v.z >= l[GTOP - 1]) continue;
        insertK<GTOP>(l, v.z);
        if (v.w < l[GTOP - 1]) insertK<GTOP>(l, v.w);
    }
#pragma unroll
    for (int d = 1; d < 32; d <<= 1) {
        uint32_t rv[GTOP];
#pragma unroll
        for (int s = 0; s < GTOP; ++s) rv[s] = __shfl_xor_sync(0xffffffffu, l[s], d);
        for (int s = 0; s < GTOP; ++s) {     // remote sorted ascending: early break
            if (rv[s] >= l[GTOP - 1]) break;
            insertK<GTOP>(l, rv[s]);
        }
    }
    if (lane == 0) {
#pragma unroll
        for (int s = 0; s < GTOP; ++s) g_cand[warp][s] = (int)(l[s] & IDXMASK);
    }
}

// ===== fused: exact fp32 re-rank -> lid_X -> z-distances -> lid_Z -> block sum =====
__global__ __launch_bounds__(256) void rerank_z_kernel(const float* __restrict__ X,
                                                       const float* __restrict__ Z) {
    __shared__ float bsum[8];
    const int warp = (blockIdx.x * blockDim.x + threadIdx.x) >> 5;
    const int lane = threadIdx.x & 31;
    const int wid = threadIdx.x >> 5;
    const int row = warp;

    float xi[8];
#pragma unroll
    for (int t = 0; t < 8; ++t) xi[t] = X[(size_t)row * DIMX + lane + 32 * t];
    const float sqr = g_sq[row];

    float lv[KNN]; int li[KNN];
#pragma unroll
    for (int s = 0; s < KNN; ++s) { lv[s] = 3.4e38f; li[s] = 0x7fffffff; }

#pragma unroll
    for (int s = 0; s < GTOP; ++s) {
        int j = g_cand[row][s];
        const float* xr = X + (size_t)j * DIMX;
        float d = 0.f;
#pragma unroll
        for (int t = 0; t < 8; ++t) d = fmaf(xi[t], xr[lane + 32 * t], d);
#pragma unroll
        for (int o = 16; o > 0; o >>= 1) d += __shfl_xor_sync(0xffffffffu, d, o);
        insert5(lv, li, sqr + g_sq[j] - 2.f * d, j);
    }

    float lidX;
    {
        float vK = sqrtf(fmaxf(lv[KNN - 1], 0.f)) + EPSF;
        float lgK = log10f(vK);
        lidX = 0.f;
#pragma unroll
        for (int s = 0; s < KNN; ++s)
            lidX += lgK - log10f(sqrtf(fmaxf(lv[s], 0.f)) + EPSF);
    }

    float z0 = Z[(size_t)row * DIMZ + lane];
    float z1 = Z[(size_t)row * DIMZ + 32 + lane];
    float e[KNN];
#pragma unroll
    for (int s = 0; s < KNN; ++s) {
        int m = li[s];
        float d0 = z0 - Z[(size_t)m * DIMZ + lane];
        float d1 = z1 - Z[(size_t)m * DIMZ + 32 + lane];
        float ss = fmaf(d0, d0, d1 * d1);
#pragma unroll
        for (int o = 16; o > 0; o >>= 1) ss += __shfl_xor_sync(0xffffffffu, ss, o);
        e[s] = sqrtf(ss) + EPSF;
    }
    float lgK = log10f(e[KNN - 1]);
    float lidZ = 0.f;
#pragma unroll
    for (int s = 0; s < KNN; ++s) lidZ += lgK - log10f(e[s]);
    float d = lidX - lidZ;

    if (lane == 0) bsum[wid] = d * d;
    __syncthreads();
    if (threadIdx.x == 0) {
        float s = 0.f;
#pragma unroll
        for (int w = 0; w < 8; ++w) s += bsum[w];
        g_bsum[blockIdx.x] = s;
    }
}

// ================= final deterministic reduction =================
__global__ void final_reduce(float* __restrict__ out) {
    __shared__ float sh[256];
    int t = threadIdx.x;
    float s = g_bsum[t] + g_bsum[t + 256] + g_bsum[t + 512] + g_bsum[t + 768];
    sh[t] = s;
    __syncthreads();
    for (int o = 128; o > 0; o >>= 1) {
        if (t < o) sh[t] += sh[t + o];
        __syncthreads();
    }
    if (t == 0) out[0] = sh[0] * (1.f / ((float)NPTS * KNN * 10.f));
}

extern "C" void kernel_launch(void* const* d_in, const int* in_sizes, int n_in,
                              void* d_out, int out_size) {
    const float* X = (const float*)d_in[0];   // (8192, 256)
    const float* Z = (const float*)d_in[1];   // (8192, 64)
    float* out = (float*)d_out;

    cvtsq_kernel<<<NPTS / 8, 256>>>(X);
    screen_pair_kernel<<<NPAIRS, 256>>>();
    merge_kernel<<<NPTS / 8, 256>>>();
    rerank_z_kernel<<<NPTS / 8, 256>>>(X, Z);
    final_reduce<<<1, 256>>>(out);
}

// round 14
// speedup vs baseline: 2.7137x; 1.0154x over previous
#include <cuda_runtime.h>
#include <cuda_bf16.h>
#include <cstdint>

#define NPTS 8192
#define DIMX 256
#define DIMZ 64
#define KNN  5
#define EPSF 1e-7f

#define NTILE 128                          // 8192 / 64 row-tiles
#define NPAIRS (NTILE * (NTILE + 1) / 2)   // 8256
#define PTOP 4
#define GTOP 8
#define U32MAX 0xFFFFFFFFu
#define IDXMASK 0x1FFFu                    // 13 bits: idx < 8192

// ---- scratch ----
__device__ float g_sq[NPTS];
__device__ __nv_bfloat16 g_xbf[NPTS * DIMX];
__device__ uint4 g_p[(size_t)NPTS * NTILE];   // 16.8 MB: 4 packed u32 keys per (row,tile)
__device__ float g_bsum[1024];

__device__ __forceinline__ uint32_t smem_u32(const void* p) {
    uint32_t a;
    asm("{ .reg .u64 t; cvta.to.shared.u64 t, %1; cvt.u32.u64 %0, t; }" : "=r"(a) : "l"(p));
    return a;
}

#define LDSM_X4(r0, r1, r2, r3, addr) \
    asm volatile("ldmatrix.sync.aligned.m8n8.x4.shared.b16 {%0,%1,%2,%3}, [%4];" \
                 : "=r"(r0), "=r"(r1), "=r"(r2), "=r"(r3) : "r"(addr))

#define MMA16816(c, a0, a1, a2, a3, b0, b1) \
    asm volatile("mma.sync.aligned.m16n8k16.row.col.f32.bf16.bf16.f32 " \
                 "{%0,%1,%2,%3}, {%4,%5,%6,%7}, {%8,%9}, {%0,%1,%2,%3};" \
                 : "+f"((c)[0]), "+f"((c)[1]), "+f"((c)[2]), "+f"((c)[3]) \
                 : "r"(a0), "r"(a1), "r"(a2), "r"(a3), "r"(b0), "r"(b1))

// monotone float->u32, top 19 bits kept; low 13 bits = idx.
// u32 '<' == (quantized value, idx) lexicographic.
__device__ __forceinline__ uint32_t packkey32(float v, int idx) {
    uint32_t u = __float_as_uint(v);
    u = (u >> 31) ? ~u : (u | 0x80000000u);
    return (u & ~IDXMASK) | (uint32_t)idx;
}
template<int NL>
__device__ __forceinline__ void insertK(uint32_t l[NL], uint32_t v) {
    if (v < l[NL - 1]) {
        l[NL - 1] = v;
#pragma unroll
        for (int s = NL - 1; s > 0; --s)
            if (l[s] < l[s - 1]) { uint32_t t = l[s]; l[s] = l[s - 1]; l[s - 1] = t; }
    }
}
__device__ __forceinline__ bool lessp(float v, int i, float v2, int i2) {
    return (v < v2) || (v == v2 && i < i2);
}
__device__ __forceinline__ void insert5(float lv[KNN], int li[KNN], float v, int idx) {
    if (lessp(v, idx, lv[KNN - 1], li[KNN - 1])) {
        lv[KNN - 1] = v; li[KNN - 1] = idx;
#pragma unroll
        for (int s = KNN - 1; s > 0; --s) {
            if (lessp(lv[s], li[s], lv[s - 1], li[s - 1])) {
                float tv = lv[s]; lv[s] = lv[s - 1]; lv[s - 1] = tv;
                int   ti = li[s]; li[s] = li[s - 1]; li[s - 1] = ti;
            }
        }
    }
}

// ================= fused fp32->bf16 + squared row norms =================
__global__ void cvtsq_kernel(const float* __restrict__ X) {
    int warp = (blockIdx.x * blockDim.x + threadIdx.x) >> 5;
    int lane = threadIdx.x & 31;
    if (warp >= NPTS) return;
    const float2* src = (const float2*)(X + (size_t)warp * DIMX);
    __nv_bfloat162* dst = (__nv_bfloat162*)(g_xbf + (size_t)warp * DIMX);
    float s = 0.f;
#pragma unroll
    for (int t = 0; t < 4; ++t) {
        float2 v = src[lane + 32 * t];
        s = fmaf(v.x, v.x, fmaf(v.y, v.y, s));
        dst[lane + 32 * t] = __floats2bfloat162_rn(v.x, v.y);
    }
#pragma unroll
    for (int o = 16; o > 0; o >>= 1) s += __shfl_xor_sync(0xffffffffu, s, o);
    if (lane == 0) g_sq[warp] = s;
}

// ====== symmetric 64x64 tile-pair screen (R13-proven, unchanged) ======
__global__ __launch_bounds__(256) void screen_pair_kernel() {
    __shared__ __align__(16) uint8_t smA[64 * 128];   // 64 rows x 64 bf16 k-chunk
    __shared__ __align__(16) uint8_t smB[64 * 128];
    __shared__ float smC[64 * 65];
    __shared__ float sqI[64], sqJ[64];

    const int tid = threadIdx.x;
    const int wid = tid >> 5;
    const int lane = tid & 31;

    // ---- linear pair index -> (ti, tj), ti <= tj ----
    const int k = blockIdx.x;
    int i = (int)(128.5f - sqrtf(128.5f * 128.5f - 2.0f * (float)k));
    if (i < 0) i = 0; if (i > NTILE - 1) i = NTILE - 1;
    while (i > 0 && (i * NTILE - i * (i - 1) / 2) > k) --i;
    while (((i + 1) * NTILE - (i + 1) * i / 2) <= k) ++i;
    const int ti = i;
    const int tj = i + (k - (i * NTILE - i * (i - 1) / 2));
    const int rbI = ti * 64, rbJ = tj * 64;

    if (tid < 64) { sqI[tid] = g_sq[rbI + tid]; sqJ[tid] = g_sq[rbJ + tid]; }

    // staging map: 512 16B-chunks per tile-chunk; thread handles chunk tid and tid+256
    const int rr = tid >> 3, cc = tid & 7;   // r in 0..31, +32 for second

    uint4 pa[2], pb[2];
#pragma unroll
    for (int it = 0; it < 2; ++it) {
        pa[it] = *(const uint4*)(g_xbf + (size_t)(rbI + rr + it * 32) * DIMX + cc * 8);
        pb[it] = *(const uint4*)(g_xbf + (size_t)(rbJ + rr + it * 32) * DIMX + cc * 8);
    }

    float c[4][4];
#pragma unroll
    for (int j = 0; j < 4; ++j)
#pragma unroll
        for (int q = 0; q < 4; ++q) c[j][q] = 0.f;

    // fragment addressing: warp (wid&3) -> row group, (wid>>2) -> col half
    const int rA = (wid & 3) * 16 + (lane & 15);
    const uint32_t aRowB = smem_u32(smA) + (uint32_t)rA * 128;
    const uint32_t aSw = (uint32_t)(rA & 7);
    const uint32_t aHi = (uint32_t)(lane >> 4);
    const int bLane = (lane & 7) + ((lane >> 4) << 3);
    const uint32_t bRowB = smem_u32(smB) + (uint32_t)bLane * 128;
    const uint32_t bSw = (uint32_t)(lane & 7);
    const uint32_t bHi = (uint32_t)((lane >> 3) & 1);
    const uint32_t bBlk = (uint32_t)(wid >> 2) * 2;   // 16-col block base

    for (int kc = 0; kc < 4; ++kc) {
        __syncthreads();
#pragma unroll
        for (int it = 0; it < 2; ++it) {
            int r = rr + it * 32;
            *(uint4*)(smA + r * 128 + (((uint32_t)cc ^ (r & 7)) << 4)) = pa[it];
            *(uint4*)(smB + r * 128 + (((uint32_t)cc ^ (r & 7)) << 4)) = pb[it];
        }
        __syncthreads();
        if (kc < 3) {
#pragma unroll
            for (int it = 0; it < 2; ++it) {
                pa[it] = *(const uint4*)(g_xbf + (size_t)(rbI + rr + it * 32) * DIMX + (kc + 1) * 64 + cc * 8);
                pb[it] = *(const uint4*)(g_xbf + (size_t)(rbJ + rr + it * 32) * DIMX + (kc + 1) * 64 + cc * 8);
            }
        }
#pragma unroll
        for (int ks = 0; ks < 4; ++ks) {
            uint32_t a0, a1, a2, a3;
            LDSM_X4(a0, a1, a2, a3, aRowB + ((((uint32_t)ks * 2 + aHi) ^ aSw) << 4));
            uint32_t ccB = (((uint32_t)ks * 2 + bHi) ^ bSw) << 4;
#pragma unroll
            for (int p = 0; p < 2; ++p) {
                uint32_t b0, b1, b2, b3;
                LDSM_X4(b0, b1, b2, b3, bRowB + (bBlk + p) * 2048 + ccB);
                MMA16816(c[2 * p],     a0, a1, a2, a3, b0, b1);
                MMA16816(c[2 * p + 1], a0, a1, a2, a3, b2, b3);
            }
        }
    }

    // ---- stage C to smem (stride 65) ----
    {
        const int r0 = (wid & 3) * 16 + (lane >> 2), r1 = r0 + 8;
        const int cq = (wid >> 2) * 32 + 2 * (lane & 3);
#pragma unroll
        for (int j = 0; j < 4; ++j) {
            int col = cq + j * 8;
            smC[r0 * 65 + col]     = c[j][0];
            smC[r0 * 65 + col + 1] = c[j][1];
            smC[r1 * 65 + col]     = c[j][2];
            smC[r1 * 65 + col + 1] = c[j][3];
        }
    }
    __syncthreads();

    // ---- row side: 4 scanners per row, 16 cols each (u32 keys) ----
    {
        const int r = tid >> 2, h = tid & 3;
        const int grow = rbI + r;
        uint32_t l[PTOP];
#pragma unroll
        for (int s = 0; s < PTOP; ++s) l[s] = U32MAX;
#pragma unroll
        for (int s = 0; s < 16; ++s) {
            int cl = h * 16 + s;
            int idx = rbJ + cl;
            if (idx != grow)
                insertK<PTOP>(l, packkey32(fmaf(-2.f, smC[r * 65 + cl], sqJ[cl]), idx));
        }
#pragma unroll
        for (int d = 1; d < 4; d <<= 1) {
            uint32_t rv[PTOP];
#pragma unroll
            for (int s = 0; s < PTOP; ++s) rv[s] = __shfl_xor_sync(0xffffffffu, l[s], d);
            for (int s = 0; s < PTOP; ++s) {          // remote sorted: early break
                if (rv[s] >= l[PTOP - 1]) break;
                insertK<PTOP>(l, rv[s]);
            }
        }
        if (h == 0)
            g_p[(size_t)grow * NTILE + tj] = make_uint4(l[0], l[1], l[2], l[3]);
    }

    // ---- col side (skip diagonal pair) ----
    if (ti != tj) {
        const int c2 = tid >> 2, h = tid & 3;
        const int grow = rbJ + c2;
        uint32_t l[PTOP];
#pragma unroll
        for (int s = 0; s < PTOP; ++s) l[s] = U32MAX;
#pragma unroll
        for (int s = 0; s < 16; ++s) {
            int rl = h * 16 + s;
            insertK<PTOP>(l, packkey32(fmaf(-2.f, smC[rl * 65 + c2], sqI[rl]), rbI + rl));
        }
#pragma unroll
        for (int d = 1; d < 4; d <<= 1) {
            uint32_t rv[PTOP];
#pragma unroll
            for (int s = 0; s < PTOP; ++s) rv[s] = __shfl_xor_sync(0xffffffffu, l[s], d);
            for (int s = 0; s < PTOP; ++s) {
                if (rv[s] >= l[PTOP - 1]) break;
                insertK<PTOP>(l, rv[s]);
            }
        }
        if (h == 0)
            g_p[(size_t)grow * NTILE + ti] = make_uint4(l[0], l[1], l[2], l[3]);
    }
}

// ===== fused: merge 128 partial lists -> exact fp32 re-rank -> lid_X ->
//        z-distances -> lid_Z -> block sum =====
__global__ __launch_bounds__(256) void merge_rerank_z_kernel(const float* __restrict__ X,
                                                             const float* __restrict__ Z) {
    __shared__ float bsum[8];
    const int warp = (blockIdx.x * blockDim.x + threadIdx.x) >> 5;
    const int lane = threadIdx.x & 31;
    const int wid = threadIdx.x >> 5;
    const int row = warp;

    // ---- merge (R13 logic, relocated): all lanes converge to the same top-8 ----
    uint32_t l[GTOP];
#pragma unroll
    for (int s = 0; s < GTOP; ++s) l[s] = U32MAX;
#pragma unroll
    for (int q = 0; q < 4; ++q) {
        uint4 v = g_p[(size_t)row * NTILE + lane + q * 32];
        // v.x < v.y < v.z < v.w (written sorted): early break
        if (v.x >= l[GTOP - 1]) continue;
        insertK<GTOP>(l, v.x);
        if (v.y >= l[GTOP - 1]) continue;
        insertK<GTOP>(l, v.y);
        if (v.z >= l[GTOP - 1]) continue;
        insertK<GTOP>(l, v.z);
        if (v.w < l[GTOP - 1]) insertK<GTOP>(l, v.w);
    }
#pragma unroll
    for (int d = 1; d < 32; d <<= 1) {
        uint32_t rv[GTOP];
#pragma unroll
        for (int s = 0; s < GTOP; ++s) rv[s] = __shfl_xor_sync(0xffffffffu, l[s], d);
        for (int s = 0; s < GTOP; ++s) {     // remote sorted ascending: early break
            if (rv[s] >= l[GTOP - 1]) break;
            insertK<GTOP>(l, rv[s]);
        }
    }
    // disjoint tile sets per lane -> unique keys; full butterfly -> identical l[] on all lanes

    // ---- exact fp32 re-rank over the 8 candidates ----
    float xi[8];
#pragma unroll
    for (int t = 0; t < 8; ++t) xi[t] = X[(size_t)row * DIMX + lane + 32 * t];
    const float sqr = g_sq[row];

    float lv[KNN]; int li[KNN];
#pragma unroll
    for (int s = 0; s < KNN; ++s) { lv[s] = 3.4e38f; li[s] = 0x7fffffff; }

#pragma unroll
    for (int s = 0; s < GTOP; ++s) {
        int j = (int)(l[s] & IDXMASK);
        const float* xr = X + (size_t)j * DIMX;
        float d = 0.f;
#pragma unroll
        for (int t = 0; t < 8; ++t) d = fmaf(xi[t], xr[lane + 32 * t], d);
#pragma unroll
        for (int o = 16; o > 0; o >>= 1) d += __shfl_xor_sync(0xffffffffu, d, o);
        insert5(lv, li, sqr + g_sq[j] - 2.f * d, j);   // identical on all lanes
    }

    float lidX;
    {
        float vK = sqrtf(fmaxf(lv[KNN - 1], 0.f)) + EPSF;
        float lgK = log10f(vK);
        lidX = 0.f;
#pragma unroll
        for (int s = 0; s < KNN; ++s)
            lidX += lgK - log10f(sqrtf(fmaxf(lv[s], 0.f)) + EPSF);
    }

    // ---- z side in the same warp (li replicated across lanes) ----
    float z0 = Z[(size_t)row * DIMZ + lane];
    float z1 = Z[(size_t)row * DIMZ + 32 + lane];
    float e[KNN];
#pragma unroll
    for (int s = 0; s < KNN; ++s) {
        int m = li[s];
        float d0 = z0 - Z[(size_t)m * DIMZ + lane];
        float d1 = z1 - Z[(size_t)m * DIMZ + 32 + lane];
        float ss = fmaf(d0, d0, d1 * d1);
#pragma unroll
        for (int o = 16; o > 0; o >>= 1) ss += __shfl_xor_sync(0xffffffffu, ss, o);
        e[s] = sqrtf(ss) + EPSF;
    }
    float lgK = log10f(e[KNN - 1]);
    float lidZ = 0.f;
#pragma unroll
    for (int s = 0; s < KNN; ++s) lidZ += lgK - log10f(e[s]);
    float d = lidX - lidZ;

    if (lane == 0) bsum[wid] = d * d;
    __syncthreads();
    if (threadIdx.x == 0) {
        float s = 0.f;
#pragma unroll
        for (int w = 0; w < 8; ++w) s += bsum[w];
        g_bsum[blockIdx.x] = s;
    }
}

// ================= final deterministic reduction =================
__global__ void final_reduce(float* __restrict__ out) {
    __shared__ float sh[256];
    int t = threadIdx.x;
    float s = g_bsum[t] + g_bsum[t + 256] + g_bsum[t + 512] + g_bsum[t + 768];
    sh[t] = s;
    __syncthreads();
    for (int o = 128; o > 0; o >>= 1) {
        if (t < o) sh[t] += sh[t + o];
        __syncthreads();
    }
    if (t == 0) out[0] = sh[0] * (1.f / ((float)NPTS * KNN * 10.f));
}

extern "C" void kernel_launch(void* const* d_in, const int* in_sizes, int n_in,
                              void* d_out, int out_size) {
    const float* X = (const float*)d_in[0];   // (8192, 256)
    const float* Z = (const float*)d_in[1];   // (8192, 64)
    float* out = (float*)d_out;

    cvtsq_kernel<<<NPTS / 8, 256>>>(X);
    screen_pair_kernel<<<NPAIRS, 256>>>();
    merge_rerank_z_kernel<<<NPTS / 8, 256>>>(X, Z);
    final_reduce<<<1, 256>>>(out);
}

// round 15
// speedup vs baseline: 2.8123x; 1.0363x over previous
#include <cuda_runtime.h>
#include <cuda_bf16.h>
#include <cstdint>

#define NPTS 8192
#define DIMX 256
#define DIMZ 64
#define KNN  5
#define EPSF 1e-7f

#define NTILE 128                          // 8192 / 64 row-tiles
#define NPAIRS (NTILE * (NTILE + 1) / 2)   // 8256
#define PTOP 4
#define GTOP 8
#define U32MAX 0xFFFFFFFFu
#define IDXMASK 0x1FFFu                    // 13 bits: idx < 8192

// ---- scratch ----
__device__ float g_sq[NPTS];
__device__ __nv_bfloat16 g_xbf[NPTS * DIMX];
__device__ uint4 g_p[(size_t)NPTS * NTILE];   // 16.8 MB: 4 packed u32 keys per (row,tile)
__device__ float g_bsum[1024];

__device__ __forceinline__ uint32_t smem_u32(const void* p) {
    uint32_t a;
    asm("{ .reg .u64 t; cvta.to.shared.u64 t, %1; cvt.u32.u64 %0, t; }" : "=r"(a) : "l"(p));
    return a;
}

#define LDSM_X4(r0, r1, r2, r3, addr) \
    asm volatile("ldmatrix.sync.aligned.m8n8.x4.shared.b16 {%0,%1,%2,%3}, [%4];" \
                 : "=r"(r0), "=r"(r1), "=r"(r2), "=r"(r3) : "r"(addr))

#define MMA16816(c, a0, a1, a2, a3, b0, b1) \
    asm volatile("mma.sync.aligned.m16n8k16.row.col.f32.bf16.bf16.f32 " \
                 "{%0,%1,%2,%3}, {%4,%5,%6,%7}, {%8,%9}, {%0,%1,%2,%3};" \
                 : "+f"((c)[0]), "+f"((c)[1]), "+f"((c)[2]), "+f"((c)[3]) \
                 : "r"(a0), "r"(a1), "r"(a2), "r"(a3), "r"(b0), "r"(b1))

// monotone float->u32, top 19 bits kept; low 13 bits = idx.
// u32 '<' == (quantized value, idx) lexicographic.
__device__ __forceinline__ uint32_t packkey32(float v, int idx) {
    uint32_t u = __float_as_uint(v);
    u = (u >> 31) ? ~u : (u | 0x80000000u);
    return (u & ~IDXMASK) | (uint32_t)idx;
}
template<int NL>
__device__ __forceinline__ void insertK(uint32_t l[NL], uint32_t v) {
    if (v < l[NL - 1]) {
        l[NL - 1] = v;
#pragma unroll
        for (int s = NL - 1; s > 0; --s)
            if (l[s] < l[s - 1]) { uint32_t t = l[s]; l[s] = l[s - 1]; l[s - 1] = t; }
    }
}
__device__ __forceinline__ bool lessp(float v, int i, float v2, int i2) {
    return (v < v2) || (v == v2 && i < i2);
}
__device__ __forceinline__ void insert5(float lv[KNN], int li[KNN], float v, int idx) {
    if (lessp(v, idx, lv[KNN - 1], li[KNN - 1])) {
        lv[KNN - 1] = v; li[KNN - 1] = idx;
#pragma unroll
        for (int s = KNN - 1; s > 0; --s) {
            if (lessp(lv[s], li[s], lv[s - 1], li[s - 1])) {
                float tv = lv[s]; lv[s] = lv[s - 1]; lv[s - 1] = tv;
                int   ti = li[s]; li[s] = li[s - 1]; li[s - 1] = ti;
            }
        }
    }
}

// ================= fused fp32->bf16 + squared row norms =================
__global__ void cvtsq_kernel(const float* __restrict__ X) {
    int warp = (blockIdx.x * blockDim.x + threadIdx.x) >> 5;
    int lane = threadIdx.x & 31;
    if (warp >= NPTS) return;
    const float2* src = (const float2*)(X + (size_t)warp * DIMX);
    __nv_bfloat162* dst = (__nv_bfloat162*)(g_xbf + (size_t)warp * DIMX);
    float s = 0.f;
#pragma unroll
    for (int t = 0; t < 4; ++t) {
        float2 v = src[lane + 32 * t];
        s = fmaf(v.x, v.x, fmaf(v.y, v.y, s));
        dst[lane + 32 * t] = __floats2bfloat162_rn(v.x, v.y);
    }
#pragma unroll
    for (int o = 16; o > 0; o >>= 1) s += __shfl_xor_sync(0xffffffffu, s, o);
    if (lane == 0) g_sq[warp] = s;
}

// ====== symmetric 64x64 tile-pair screen: register-direct row side ======
__global__ __launch_bounds__(256) void screen_pair_kernel() {
    __shared__ __align__(16) uint8_t smA[64 * 128];   // 64 rows x 64 bf16 k-chunk
    __shared__ __align__(16) uint8_t smB[64 * 128];
    __shared__ float smC[64 * 65];
    __shared__ float sqI[64], sqJ[64];
    __shared__ uint4 smH[64];                         // row-side half-1 lists

    const int tid = threadIdx.x;
    const int wid = tid >> 5;
    const int lane = tid & 31;

    // ---- linear pair index -> (ti, tj), ti <= tj ----
    const int k = blockIdx.x;
    int i = (int)(128.5f - sqrtf(128.5f * 128.5f - 2.0f * (float)k));
    if (i < 0) i = 0; if (i > NTILE - 1) i = NTILE - 1;
    while (i > 0 && (i * NTILE - i * (i - 1) / 2) > k) --i;
    while (((i + 1) * NTILE - (i + 1) * i / 2) <= k) ++i;
    const int ti = i;
    const int tj = i + (k - (i * NTILE - i * (i - 1) / 2));
    const int rbI = ti * 64, rbJ = tj * 64;

    if (tid < 64) { sqI[tid] = g_sq[rbI + tid]; sqJ[tid] = g_sq[rbJ + tid]; }

    // staging map: 512 16B-chunks per tile-chunk; thread handles chunk tid and tid+256
    const int rr = tid >> 3, cc = tid & 7;   // r in 0..31, +32 for second

    uint4 pa[2], pb[2];
#pragma unroll
    for (int it = 0; it < 2; ++it) {
        pa[it] = *(const uint4*)(g_xbf + (size_t)(rbI + rr + it * 32) * DIMX + cc * 8);
        pb[it] = *(const uint4*)(g_xbf + (size_t)(rbJ + rr + it * 32) * DIMX + cc * 8);
    }

    float c[4][4];
#pragma unroll
    for (int j = 0; j < 4; ++j)
#pragma unroll
        for (int q = 0; q < 4; ++q) c[j][q] = 0.f;

    // fragment addressing: warp (wid&3) -> row group, (wid>>2) -> col half
    const int rA = (wid & 3) * 16 + (lane & 15);
    const uint32_t aRowB = smem_u32(smA) + (uint32_t)rA * 128;
    const uint32_t aSw = (uint32_t)(rA & 7);
    const uint32_t aHi = (uint32_t)(lane >> 4);
    const int bLane = (lane & 7) + ((lane >> 4) << 3);
    const uint32_t bRowB = smem_u32(smB) + (uint32_t)bLane * 128;
    const uint32_t bSw = (uint32_t)(lane & 7);
    const uint32_t bHi = (uint32_t)((lane >> 3) & 1);
    const uint32_t bBlk = (uint32_t)(wid >> 2) * 2;   // 16-col block base

    for (int kc = 0; kc < 4; ++kc) {
        __syncthreads();
#pragma unroll
        for (int it = 0; it < 2; ++it) {
            int r = rr + it * 32;
            *(uint4*)(smA + r * 128 + (((uint32_t)cc ^ (r & 7)) << 4)) = pa[it];
            *(uint4*)(smB + r * 128 + (((uint32_t)cc ^ (r & 7)) << 4)) = pb[it];
        }
        __syncthreads();
        if (kc < 3) {
#pragma unroll
            for (int it = 0; it < 2; ++it) {
                pa[it] = *(const uint4*)(g_xbf + (size_t)(rbI + rr + it * 32) * DIMX + (kc + 1) * 64 + cc * 8);
                pb[it] = *(const uint4*)(g_xbf + (size_t)(rbJ + rr + it * 32) * DIMX + (kc + 1) * 64 + cc * 8);
            }
        }
#pragma unroll
        for (int ks = 0; ks < 4; ++ks) {
            uint32_t a0, a1, a2, a3;
            LDSM_X4(a0, a1, a2, a3, aRowB + ((((uint32_t)ks * 2 + aHi) ^ aSw) << 4));
            uint32_t ccB = (((uint32_t)ks * 2 + bHi) ^ bSw) << 4;
#pragma unroll
            for (int p = 0; p < 2; ++p) {
                uint32_t b0, b1, b2, b3;
                LDSM_X4(b0, b1, b2, b3, bRowB + (bBlk + p) * 2048 + ccB);
                MMA16816(c[2 * p],     a0, a1, a2, a3, b0, b1);
                MMA16816(c[2 * p + 1], a0, a1, a2, a3, b2, b3);
            }
        }
    }
    __syncthreads();   // LDSM reads done; safe to write smC/smH below

    // ---- stage C to smem (stride 65) for the col-side scan ----
    const int rloc0 = (wid & 3) * 16 + (lane >> 2), rloc1 = rloc0 + 8;
    const int cq = (wid >> 2) * 32 + 2 * (lane & 3);
#pragma unroll
    for (int j = 0; j < 4; ++j) {
        int col = cq + j * 8;
        smC[rloc0 * 65 + col]     = c[j][0];
        smC[rloc0 * 65 + col + 1] = c[j][1];
        smC[rloc1 * 65 + col]     = c[j][2];
        smC[rloc1 * 65 + col + 1] = c[j][3];
    }

    // ---- row side DIRECT FROM REGISTERS: top-4 over this thread's 8 cols ----
    const int grow0 = rbI + rloc0, grow1 = rbI + rloc1;
    uint32_t l0[PTOP], l1[PTOP];
#pragma unroll
    for (int s = 0; s < PTOP; ++s) { l0[s] = U32MAX; l1[s] = U32MAX; }
#pragma unroll
    for (int j = 0; j < 4; ++j) {
        int c0 = cq + j * 8, c1 = c0 + 1;
        int i0 = rbJ + c0, i1 = rbJ + c1;
        float sq0 = sqJ[c0], sq1 = sqJ[c1];
        if (i0 != grow0) insertK<PTOP>(l0, packkey32(fmaf(-2.f, c[j][0], sq0), i0));
        if (i1 != grow0) insertK<PTOP>(l0, packkey32(fmaf(-2.f, c[j][1], sq1), i1));
        if (i0 != grow1) insertK<PTOP>(l1, packkey32(fmaf(-2.f, c[j][2], sq0), i0));
        if (i1 != grow1) insertK<PTOP>(l1, packkey32(fmaf(-2.f, c[j][3], sq1), i1));
    }
    // quad merge across lane&3 (covers the 32 cols of this warp's half)
#pragma unroll
    for (int d = 1; d < 4; d <<= 1) {
        uint32_t rv0[PTOP], rv1[PTOP];
#pragma unroll
        for (int s = 0; s < PTOP; ++s) {
            rv0[s] = __shfl_xor_sync(0xffffffffu, l0[s], d);
            rv1[s] = __shfl_xor_sync(0xffffffffu, l1[s], d);
        }
        for (int s = 0; s < PTOP; ++s) {
            if (rv0[s] >= l0[PTOP - 1]) break;
            insertK<PTOP>(l0, rv0[s]);
        }
        for (int s = 0; s < PTOP; ++s) {
            if (rv1[s] >= l1[PTOP - 1]) break;
            insertK<PTOP>(l1, rv1[s]);
        }
    }
    // half-1 warps publish their per-row lists
    if ((wid >> 2) == 1 && (lane & 3) == 0) {
        smH[rloc0] = make_uint4(l0[0], l0[1], l0[2], l0[3]);
        smH[rloc1] = make_uint4(l1[0], l1[1], l1[2], l1[3]);
    }
    __syncthreads();   // smH + smC visible

    // half-0 warps fold partner half and store row-side partials
    if ((wid >> 2) == 0 && (lane & 3) == 0) {
        uint4 h0 = smH[rloc0];
        {
            if (h0.x < l0[PTOP - 1]) { insertK<PTOP>(l0, h0.x);
            if (h0.y < l0[PTOP - 1]) { insertK<PTOP>(l0, h0.y);
            if (h0.z < l0[PTOP - 1]) { insertK<PTOP>(l0, h0.z);
            if (h0.w < l0[PTOP - 1]) { insertK<PTOP>(l0, h0.w); } } } }
        }
        uint4 h1 = smH[rloc1];
        {
            if (h1.x < l1[PTOP - 1]) { insertK<PTOP>(l1, h1.x);
            if (h1.y < l1[PTOP - 1]) { insertK<PTOP>(l1, h1.y);
            if (h1.z < l1[PTOP - 1]) { insertK<PTOP>(l1, h1.z);
            if (h1.w < l1[PTOP - 1]) { insertK<PTOP>(l1, h1.w); } } } }
        }
        g_p[(size_t)grow0 * NTILE + tj] = make_uint4(l0[0], l0[1], l0[2], l0[3]);
        g_p[(size_t)grow1 * NTILE + tj] = make_uint4(l1[0], l1[1], l1[2], l1[3]);
    }

    // ---- col side (unchanged; skip diagonal pair) ----
    if (ti != tj) {
        const int c2 = tid >> 2, h = tid & 3;
        const int grow = rbJ + c2;
        uint32_t l[PTOP];
#pragma unroll
        for (int s = 0; s < PTOP; ++s) l[s] = U32MAX;
#pragma unroll
        for (int s = 0; s < 16; ++s) {
            int rl = h * 16 + s;
            insertK<PTOP>(l, packkey32(fmaf(-2.f, smC[rl * 65 + c2], sqI[rl]), rbI + rl));
        }
#pragma unroll
        for (int d = 1; d < 4; d <<= 1) {
            uint32_t rv[PTOP];
#pragma unroll
            for (int s = 0; s < PTOP; ++s) rv[s] = __shfl_xor_sync(0xffffffffu, l[s], d);
            for (int s = 0; s < PTOP; ++s) {
                if (rv[s] >= l[PTOP - 1]) break;
                insertK<PTOP>(l, rv[s]);
            }
        }
        if (h == 0)
            g_p[(size_t)grow * NTILE + ti] = make_uint4(l[0], l[1], l[2], l[3]);
    }
}

// ===== fused: merge 128 partial lists -> exact fp32 re-rank -> lid_X ->
//        z-distances -> lid_Z -> block sum =====
__global__ __launch_bounds__(256) void merge_rerank_z_kernel(const float* __restrict__ X,
                                                             const float* __restrict__ Z) {
    __shared__ float bsum[8];
    const int warp = (blockIdx.x * blockDim.x + threadIdx.x) >> 5;
    const int lane = threadIdx.x & 31;
    const int wid = threadIdx.x >> 5;
    const int row = warp;

    uint32_t l[GTOP];
#pragma unroll
    for (int s = 0; s < GTOP; ++s) l[s] = U32MAX;
#pragma unroll
    for (int q = 0; q < 4; ++q) {
        uint4 v = g_p[(size_t)row * NTILE + lane + q * 32];
        if (v.x >= l[GTOP - 1]) continue;
        insertK<GTOP>(l, v.x);
        if (v.y >= l[GTOP - 1]) continue;
        insertK<GTOP>(l, v.y);
        if (v.z >= l[GTOP - 1]) continue;
        insertK<GTOP>(l, v.z);
        if (v.w < l[GTOP - 1]) insertK<GTOP>(l, v.w);
    }
#pragma unroll
    for (int d = 1; d < 32; d <<= 1) {
        uint32_t rv[GTOP];
#pragma unroll
        for (int s = 0; s < GTOP; ++s) rv[s] = __shfl_xor_sync(0xffffffffu, l[s], d);
        for (int s = 0; s < GTOP; ++s) {
            if (rv[s] >= l[GTOP - 1]) break;
            insertK<GTOP>(l, rv[s]);
        }
    }

    float xi[8];
#pragma unroll
    for (int t = 0; t < 8; ++t) xi[t] = X[(size_t)row * DIMX + lane + 32 * t];
    const float sqr = g_sq[row];

    float lv[KNN]; int li[KNN];
#pragma unroll
    for (int s = 0; s < KNN; ++s) { lv[s] = 3.4e38f; li[s] = 0x7fffffff; }

#pragma unroll
    for (int s = 0; s < GTOP; ++s) {
        int j = (int)(l[s] & IDXMASK);
        const float* xr = X + (size_t)j * DIMX;
        float d = 0.f;
#pragma unroll
        for (int t = 0; t < 8; ++t) d = fmaf(xi[t], xr[lane + 32 * t], d);
#pragma unroll
        for (int o = 16; o > 0; o >>= 1) d += __shfl_xor_sync(0xffffffffu, d, o);
        insert5(lv, li, sqr + g_sq[j] - 2.f * d, j);
    }

    float lidX;
    {
        float vK = sqrtf(fmaxf(lv[KNN - 1], 0.f)) + EPSF;
        float lgK = log10f(vK);
        lidX = 0.f;
#pragma unroll
        for (int s = 0; s < KNN; ++s)
            lidX += lgK - log10f(sqrtf(fmaxf(lv[s], 0.f)) + EPSF);
    }

    float z0 = Z[(size_t)row * DIMZ + lane];
    float z1 = Z[(size_t)row * DIMZ + 32 + lane];
    float e[KNN];
#pragma unroll
    for (int s = 0; s < KNN; ++s) {
        int m = li[s];
        float d0 = z0 - Z[(size_t)m * DIMZ + lane];
        float d1 = z1 - Z[(size_t)m * DIMZ + 32 + lane];
        float ss = fmaf(d0, d0, d1 * d1);
#pragma unroll
        for (int o = 16; o > 0; o >>= 1) ss += __shfl_xor_sync(0xffffffffu, ss, o);
        e[s] = sqrtf(ss) + EPSF;
    }
    float lgK = log10f(e[KNN - 1]);
    float lidZ = 0.f;
#pragma unroll
    for (int s = 0; s < KNN; ++s) lidZ += lgK - log10f(e[s]);
    float d = lidX - lidZ;

    if (lane == 0) bsum[wid] = d * d;
    __syncthreads();
    if (threadIdx.x == 0) {
        float s = 0.f;
#pragma unroll
        for (int w = 0; w < 8; ++w) s += bsum[w];
        g_bsum[blockIdx.x] = s;
    }
}

// ================= final deterministic reduction =================
__global__ void final_reduce(float* __restrict__ out) {
    __shared__ float sh[256];
    int t = threadIdx.x;
    float s = g_bsum[t] + g_bsum[t + 256] + g_bsum[t + 512] + g_bsum[t + 768];
    sh[t] = s;
    __syncthreads();
    for (int o = 128; o > 0; o >>= 1) {
        if (t < o) sh[t] += sh[t + o];
        __syncthreads();
    }
    if (t == 0) out[0] = sh[0] * (1.f / ((float)NPTS * KNN * 10.f));
}

extern "C" void kernel_launch(void* const* d_in, const int* in_sizes, int n_in,
                              void* d_out, int out_size) {
    const float* X = (const float*)d_in[0];   // (8192, 256)
    const float* Z = (const float*)d_in[1];   // (8192, 64)
    float* out = (float*)d_out;

    cvtsq_kernel<<<NPTS / 8, 256>>>(X);
    screen_pair_kernel<<<NPAIRS, 256>>>();
    merge_rerank_z_kernel<<<NPTS / 8, 256>>>(X, Z);
    final_reduce<<<1, 256>>>(out);
}